// round 1
// baseline (speedup 1.0000x reference)
#include <cuda_runtime.h>
#include <cuda_bf16.h>
#include <math.h>

// Problem constants
#define BATCH 8
#define SEQ 512
#define DIM 768
#define NHEAD 12
#define DH 64
#define INNER 768
#define MLPDIM 3072
#define DEPTH 4
#define ROWS (BATCH * SEQ)          // 4096
#define LSCALE 0.1f
#define EPS 1e-5f
#define ATT_SCALE 0.125f            // 64^-0.5

// GEMM tiling
#define BM 64
#define BN 64
#define BK 16

// -------- scratch buffers (device globals; allocation-free) --------
__device__ float g_h   [ROWS * DIM];          // LN output
__device__ float g_q   [ROWS * INNER];
__device__ float g_kv  [ROWS * 2 * INNER];
__device__ float g_dots [BATCH * NHEAD * SEQ * SEQ];   // 25,165,824
__device__ float g_dots2[BATCH * NHEAD * SEQ * SEQ];
__device__ float g_o   [ROWS * INNER];
__device__ float g_mlp [ROWS * MLPDIM];

__device__ __forceinline__ float gelu_tanh(float x) {
    float x3 = x * x * x;
    return 0.5f * x * (1.0f + tanhf(0.7978845608028654f * (x + 0.044715f * x3)));
}

// ---------------- LayerNorm (use_bias=False) ----------------
// one block per row, 256 threads
__global__ void ln_kernel(const float* __restrict__ x, const float* __restrict__ scale,
                          float* __restrict__ out) {
    int row = blockIdx.x;
    const float* xr = x + (size_t)row * DIM;
    float* outr = out + (size_t)row * DIM;
    int tid = threadIdx.x;

    float s = 0.f, s2 = 0.f;
    for (int c = tid; c < DIM; c += 256) {
        float v = xr[c];
        s += v; s2 += v * v;
    }
    __shared__ float rs[256];
    __shared__ float rs2[256];
    rs[tid] = s; rs2[tid] = s2;
    __syncthreads();
    for (int off = 128; off > 0; off >>= 1) {
        if (tid < off) { rs[tid] += rs[tid + off]; rs2[tid] += rs2[tid + off]; }
        __syncthreads();
    }
    float mu = rs[0] * (1.0f / DIM);
    float var = rs2[0] * (1.0f / DIM) - mu * mu;
    float rstd = rsqrtf(var + EPS);
    for (int c = tid; c < DIM; c += 256) {
        outr[c] = (xr[c] - mu) * rstd * scale[c];
    }
}

// ---------------- Generic tiled SGEMM ----------------
// C[M,N] = A[M,K] @ B[K,N], row-major.
// epi: 0 -> C = acc
//      1 -> C = gelu(acc + bias[n])
//      2 -> X[m,n] = (acc + bias[n]) * LSCALE + X[m,n]   (residual in/out)
__global__ void gemm_kernel(const float* __restrict__ A, const float* __restrict__ B,
                            const float* __restrict__ bias,
                            float* __restrict__ C, float* __restrict__ X,
                            int M, int N, int K, int epi) {
    __shared__ float As[BK][BM + 1];
    __shared__ float Bs[BK][BN];
    int tid = threadIdx.x;
    int tx = tid & 15;         // 0..15 -> col group
    int ty = tid >> 4;         // 0..15 -> row group
    int row0 = blockIdx.y * BM;
    int col0 = blockIdx.x * BN;

    float acc[4][4] = {};
    for (int k0 = 0; k0 < K; k0 += BK) {
        #pragma unroll
        for (int i = tid; i < BM * BK; i += 256) {
            int r = i >> 4, c = i & 15;
            As[c][r] = A[(size_t)(row0 + r) * K + (k0 + c)];
        }
        #pragma unroll
        for (int i = tid; i < BK * BN; i += 256) {
            int r = i >> 6, c = i & 63;
            Bs[r][c] = B[(size_t)(k0 + r) * N + (col0 + c)];
        }
        __syncthreads();
        #pragma unroll
        for (int kk = 0; kk < BK; kk++) {
            float ra[4], rb[4];
            #pragma unroll
            for (int a = 0; a < 4; a++) ra[a] = As[kk][ty * 4 + a];
            #pragma unroll
            for (int b = 0; b < 4; b++) rb[b] = Bs[kk][tx * 4 + b];
            #pragma unroll
            for (int a = 0; a < 4; a++)
                #pragma unroll
                for (int b = 0; b < 4; b++)
                    acc[a][b] += ra[a] * rb[b];
        }
        __syncthreads();
    }

    #pragma unroll
    for (int a = 0; a < 4; a++) {
        int r = row0 + ty * 4 + a;
        #pragma unroll
        for (int b = 0; b < 4; b++) {
            int c = col0 + tx * 4 + b;
            float v = acc[a][b];
            if (epi == 0) {
                C[(size_t)r * N + c] = v;
            } else if (epi == 1) {
                C[(size_t)r * N + c] = gelu_tanh(v + bias[c]);
            } else {
                size_t idx = (size_t)r * N + c;
                X[idx] = (v + bias[c]) * LSCALE + X[idx];
            }
        }
    }
}

// ---------------- QK^T batched ----------------
// dots[b,h,i,j] = scale * sum_d q[b,i,h*64+d] * k[b,j,h*64+d]
// grid: (j_tiles=8, i_tiles=8, b*h=96), 256 threads
__global__ void qk_kernel(const float* __restrict__ q, const float* __restrict__ kv,
                          float* __restrict__ dots) {
    __shared__ float As[BK][BM + 1];   // [d][i]
    __shared__ float Bs[BK][BN + 1];   // [d][j]
    int tid = threadIdx.x;
    int tx = tid & 15, ty = tid >> 4;
    int bh = blockIdx.z;
    int b = bh / NHEAD, h = bh % NHEAD;
    int i0 = blockIdx.y * BM;
    int j0 = blockIdx.x * BN;

    const float* qbase = q + (size_t)b * SEQ * INNER + h * DH;
    const float* kbase = kv + (size_t)b * SEQ * (2 * INNER) + h * DH;

    float acc[4][4] = {};
    for (int k0 = 0; k0 < DH; k0 += BK) {
        #pragma unroll
        for (int i = tid; i < BM * BK; i += 256) {
            int r = i >> 4, c = i & 15;
            As[c][r] = qbase[(size_t)(i0 + r) * INNER + (k0 + c)];
        }
        #pragma unroll
        for (int i = tid; i < BN * BK; i += 256) {
            int r = i >> 4, c = i & 15;
            Bs[c][r] = kbase[(size_t)(j0 + r) * (2 * INNER) + (k0 + c)];
        }
        __syncthreads();
        #pragma unroll
        for (int kk = 0; kk < BK; kk++) {
            float ra[4], rb[4];
            #pragma unroll
            for (int a = 0; a < 4; a++) ra[a] = As[kk][ty * 4 + a];
            #pragma unroll
            for (int b2 = 0; b2 < 4; b2++) rb[b2] = Bs[kk][tx * 4 + b2];
            #pragma unroll
            for (int a = 0; a < 4; a++)
                #pragma unroll
                for (int b2 = 0; b2 < 4; b2++)
                    acc[a][b2] += ra[a] * rb[b2];
        }
        __syncthreads();
    }

    float* dbase = dots + ((size_t)bh * SEQ + i0) * SEQ + j0;
    #pragma unroll
    for (int a = 0; a < 4; a++)
        #pragma unroll
        for (int b2 = 0; b2 < 4; b2++)
            dbase[(size_t)(ty * 4 + a) * SEQ + (tx * 4 + b2)] = acc[a][b2] * ATT_SCALE;
}

// ---------------- talking-heads mix ----------------
// out[b,g,i,j] = sum_h in[b,h,i,j] * m[h,g]
__global__ void mix_kernel(const float* __restrict__ in, const float* __restrict__ mat,
                           float* __restrict__ out) {
    __shared__ float m[NHEAD * NHEAD];
    if (threadIdx.x < NHEAD * NHEAD) m[threadIdx.x] = mat[threadIdx.x];
    __syncthreads();
    size_t pos = (size_t)blockIdx.x * 256 + threadIdx.x;   // over b*i*j = 2,097,152
    int b = (int)(pos >> 18);
    size_t rem = pos & 262143;
    size_t base = (size_t)b * NHEAD * 262144 + rem;
    float vin[NHEAD];
    #pragma unroll
    for (int h = 0; h < NHEAD; h++) vin[h] = in[base + (size_t)h * 262144];
    #pragma unroll
    for (int g = 0; g < NHEAD; g++) {
        float acc = 0.f;
        #pragma unroll
        for (int h = 0; h < NHEAD; h++) acc += vin[h] * m[h * NHEAD + g];
        out[base + (size_t)g * 262144] = acc;
    }
}

// ---------------- softmax in-place over last dim (512) ----------------
__global__ void softmax_kernel(float* __restrict__ p) {
    size_t row = blockIdx.x;
    float* pr = p + row * SEQ;
    int tid = threadIdx.x;
    __shared__ float red[256];

    float mx = -1e30f;
    for (int c = tid; c < SEQ; c += 256) mx = fmaxf(mx, pr[c]);
    red[tid] = mx; __syncthreads();
    for (int off = 128; off > 0; off >>= 1) {
        if (tid < off) red[tid] = fmaxf(red[tid], red[tid + off]);
        __syncthreads();
    }
    mx = red[0];
    __syncthreads();

    float s = 0.f;
    float vals[2];
    #pragma unroll
    for (int k = 0; k < 2; k++) {
        int c = tid + k * 256;
        float e = __expf(pr[c] - mx);
        vals[k] = e; s += e;
    }
    red[tid] = s; __syncthreads();
    for (int off = 128; off > 0; off >>= 1) {
        if (tid < off) red[tid] += red[tid + off];
        __syncthreads();
    }
    float inv = 1.0f / red[0];
    #pragma unroll
    for (int k = 0; k < 2; k++) {
        int c = tid + k * 256;
        pr[c] = vals[k] * inv;
    }
}

// ---------------- attn @ V batched ----------------
// o[b,i,h*64+d] = sum_j attn[b,h,i,j] * v[b,j,h*64+d]
// grid: (i_tiles=8, b*h=96)
__global__ void av_kernel(const float* __restrict__ attn, const float* __restrict__ kv,
                          float* __restrict__ o) {
    __shared__ float As[BK][BM + 1];   // [j][i]
    __shared__ float Bs[BK][BN];       // [j][d]
    int tid = threadIdx.x;
    int tx = tid & 15, ty = tid >> 4;
    int bh = blockIdx.y;
    int b = bh / NHEAD, h = bh % NHEAD;
    int i0 = blockIdx.x * BM;

    const float* abase = attn + (size_t)bh * SEQ * SEQ;
    const float* vbase = kv + (size_t)b * SEQ * (2 * INNER) + INNER + h * DH;

    float acc[4][4] = {};
    for (int k0 = 0; k0 < SEQ; k0 += BK) {
        #pragma unroll
        for (int i = tid; i < BM * BK; i += 256) {
            int r = i >> 4, c = i & 15;
            As[c][r] = abase[(size_t)(i0 + r) * SEQ + (k0 + c)];
        }
        #pragma unroll
        for (int i = tid; i < BK * BN; i += 256) {
            int r = i >> 6, c = i & 63;
            Bs[r][c] = vbase[(size_t)(k0 + r) * (2 * INNER) + c];
        }
        __syncthreads();
        #pragma unroll
        for (int kk = 0; kk < BK; kk++) {
            float ra[4], rb[4];
            #pragma unroll
            for (int a = 0; a < 4; a++) ra[a] = As[kk][ty * 4 + a];
            #pragma unroll
            for (int b2 = 0; b2 < 4; b2++) rb[b2] = Bs[kk][tx * 4 + b2];
            #pragma unroll
            for (int a = 0; a < 4; a++)
                #pragma unroll
                for (int b2 = 0; b2 < 4; b2++)
                    acc[a][b2] += ra[a] * rb[b2];
        }
        __syncthreads();
    }

    float* obase = o + ((size_t)b * SEQ + i0) * INNER + h * DH;
    #pragma unroll
    for (int a = 0; a < 4; a++)
        #pragma unroll
        for (int b2 = 0; b2 < 4; b2++)
            obase[(size_t)(ty * 4 + a) * INNER + (tx * 4 + b2)] = acc[a][b2];
}

// ---------------- launch ----------------
extern "C" void kernel_launch(void* const* d_in, const int* in_sizes, int n_in,
                              void* d_out, int out_size) {
    const float* x_in     = (const float*)d_in[0];
    const float* ln1      = (const float*)d_in[1];
    const float* Wq       = (const float*)d_in[2];
    const float* Wkv      = (const float*)d_in[3];
    const float* mix_pre  = (const float*)d_in[4];
    const float* mix_post = (const float*)d_in[5];
    const float* Wo       = (const float*)d_in[6];
    const float* bo       = (const float*)d_in[7];
    const float* ln2      = (const float*)d_in[8];
    const float* W1       = (const float*)d_in[9];
    const float* b1       = (const float*)d_in[10];
    const float* W2       = (const float*)d_in[11];
    const float* b2       = (const float*)d_in[12];

    float* X = (float*)d_out;   // residual stream lives in d_out

    float *h, *q, *kv, *dots, *dots2, *o, *mlp;
    cudaGetSymbolAddress((void**)&h,     g_h);
    cudaGetSymbolAddress((void**)&q,     g_q);
    cudaGetSymbolAddress((void**)&kv,    g_kv);
    cudaGetSymbolAddress((void**)&dots,  g_dots);
    cudaGetSymbolAddress((void**)&dots2, g_dots2);
    cudaGetSymbolAddress((void**)&o,     g_o);
    cudaGetSymbolAddress((void**)&mlp,   g_mlp);

    cudaMemcpyAsync(X, x_in, (size_t)ROWS * DIM * sizeof(float),
                    cudaMemcpyDeviceToDevice);

    for (int d = 0; d < DEPTH; d++) {
        // --- attention half ---
        ln_kernel<<<ROWS, 256>>>(X, ln1 + d * DIM, h);

        dim3 gq(INNER / BN, ROWS / BM);
        gemm_kernel<<<gq, 256>>>(h, Wq + (size_t)d * DIM * INNER, nullptr,
                                 q, nullptr, ROWS, INNER, DIM, 0);
        dim3 gkv(2 * INNER / BN, ROWS / BM);
        gemm_kernel<<<gkv, 256>>>(h, Wkv + (size_t)d * DIM * 2 * INNER, nullptr,
                                  kv, nullptr, ROWS, 2 * INNER, DIM, 0);

        dim3 gqk(SEQ / BN, SEQ / BM, BATCH * NHEAD);
        qk_kernel<<<gqk, 256>>>(q, kv, dots);

        mix_kernel<<<(BATCH * SEQ * SEQ) / 256, 256>>>(dots, mix_pre + d * NHEAD * NHEAD, dots2);
        softmax_kernel<<<BATCH * NHEAD * SEQ, 256>>>(dots2);
        mix_kernel<<<(BATCH * SEQ * SEQ) / 256, 256>>>(dots2, mix_post + d * NHEAD * NHEAD, dots);

        dim3 gav(SEQ / BM, BATCH * NHEAD);
        av_kernel<<<gav, 256>>>(dots, kv, o);

        dim3 go(DIM / BN, ROWS / BM);
        gemm_kernel<<<go, 256>>>(o, Wo + (size_t)d * INNER * DIM, bo + d * DIM,
                                 nullptr, X, ROWS, DIM, INNER, 2);

        // --- MLP half ---
        ln_kernel<<<ROWS, 256>>>(X, ln2 + d * DIM, h);

        dim3 g1(MLPDIM / BN, ROWS / BM);
        gemm_kernel<<<g1, 256>>>(h, W1 + (size_t)d * DIM * MLPDIM, b1 + d * MLPDIM,
                                 mlp, nullptr, ROWS, MLPDIM, DIM, 1);
        dim3 g2(DIM / BN, ROWS / BM);
        gemm_kernel<<<g2, 256>>>(mlp, W2 + (size_t)d * MLPDIM * DIM, b2 + d * DIM,
                                 nullptr, X, ROWS, DIM, MLPDIM, 2);
    }
}

// round 2
// speedup vs baseline: 1.1837x; 1.1837x over previous
#include <cuda_runtime.h>
#include <cuda_bf16.h>
#include <math.h>

// Problem constants
#define BATCH 8
#define SEQ 512
#define DIM 768
#define NHEAD 12
#define DH 64
#define INNER 768
#define MLPDIM 3072
#define DEPTH 4
#define ROWS (BATCH * SEQ)          // 4096
#define LSCALE 0.1f
#define EPS 1e-5f
#define ATT_SCALE 0.125f            // 64^-0.5

// -------- scratch buffers (device globals; allocation-free) --------
__device__ float g_h   [ROWS * DIM];
__device__ float g_q   [ROWS * INNER];
__device__ float g_kv  [ROWS * 2 * INNER];
__device__ float g_dots[BATCH * NHEAD * SEQ * SEQ];
__device__ float g_o   [ROWS * INNER];
__device__ float g_mlp [ROWS * MLPDIM];

__device__ __forceinline__ float gelu_tanh(float x) {
    float x3 = x * x * x;
    return 0.5f * x * (1.0f + tanhf(0.7978845608028654f * (x + 0.044715f * x3)));
}

__device__ __forceinline__ void tf32_split(float x, unsigned& hi, unsigned& lo) {
    asm("cvt.rna.tf32.f32 %0, %1;" : "=r"(hi) : "f"(x));
    float rem = x - __uint_as_float(hi);
    asm("cvt.rna.tf32.f32 %0, %1;" : "=r"(lo) : "f"(rem));
}

#define MMA8(d, a, b) \
    asm volatile("mma.sync.aligned.m16n8k8.row.col.f32.tf32.tf32.f32 " \
                 "{%0,%1,%2,%3},{%4,%5,%6,%7},{%8,%9},{%0,%1,%2,%3};" \
                 : "+f"(d[0]), "+f"(d[1]), "+f"(d[2]), "+f"(d[3])     \
                 : "r"(a[0]), "r"(a[1]), "r"(a[2]), "r"(a[3]),        \
                   "r"(b[0]), "r"(b[1]))

// ---------------- LayerNorm ----------------
__global__ __launch_bounds__(256) void ln_kernel(const float* __restrict__ x,
                                                 const float* __restrict__ scale,
                                                 float* __restrict__ out) {
    int row = blockIdx.x;
    const float* xr = x + (size_t)row * DIM;
    float* outr = out + (size_t)row * DIM;
    int tid = threadIdx.x;

    float s = 0.f, s2 = 0.f;
    for (int c = tid; c < DIM; c += 256) {
        float v = xr[c];
        s += v; s2 += v * v;
    }
    __shared__ float rs[256];
    __shared__ float rs2[256];
    rs[tid] = s; rs2[tid] = s2;
    __syncthreads();
    for (int off = 128; off > 0; off >>= 1) {
        if (tid < off) { rs[tid] += rs[tid + off]; rs2[tid] += rs2[tid + off]; }
        __syncthreads();
    }
    float mu = rs[0] * (1.0f / DIM);
    float var = rs2[0] * (1.0f / DIM) - mu * mu;
    float rstd = rsqrtf(var + EPS);
    for (int c = tid; c < DIM; c += 256) {
        outr[c] = (xr[c] - mu) * rstd * scale[c];
    }
}

// ---------------- Tensor-core GEMM (3xTF32 split) ----------------
// C[M,N] = alpha * A[M,K] @ B, row-major A. B row-major [K,N] (transB=0) or
// B[n,k] layout (transB=1, i.e. C = A @ B^T with B rows = n).
// Batched over blockIdx.z = bz*nH + hz with independent strides.
// epi: 0 -> C = alpha*acc
//      1 -> C = gelu(acc + bias[n])
//      2 -> C[idx] += (acc + bias[n]) * LSCALE   (residual; C is X)
template<int BM, int BN, int WARPS_M, int WARPS_N>
__global__ __launch_bounds__(256) void tgemm(
    const float* __restrict__ A, int lda, long sAb, long sAh,
    const float* __restrict__ B, int ldb, long sBb, long sBh, int transB,
    float* __restrict__ Cx, int ldc, long sCb, long sCh,
    const float* __restrict__ bias,
    int M, int N, int K, int nH, float alpha, int epi)
{
    constexpr int BK = 16;
    constexpr int WM = BM / WARPS_M;
    constexpr int WN = BN / WARPS_N;
    constexpr int MF = WM / 16;
    constexpr int NF = WN / 8;
    constexpr int NT = WARPS_M * WARPS_N * 32;   // 256

    __shared__ unsigned Ah[BK][BM + 4], Al[BK][BM + 4];
    __shared__ unsigned Bh[BK][BN + 4], Bl[BK][BN + 4];

    int tid = threadIdx.x, lane = tid & 31, warp = tid >> 5;
    int wm = warp / WARPS_N, wn = warp % WARPS_N;
    int bz = blockIdx.z / nH, hz = blockIdx.z % nH;
    const float* Ab = A + (size_t)bz * sAb + (size_t)hz * sAh
                        + (size_t)blockIdx.y * BM * lda;
    const float* Bb = B + (size_t)bz * sBb + (size_t)hz * sBh;
    int n0 = blockIdx.x * BN;

    float acc[MF][NF][4] = {};

    for (int k0 = 0; k0 < K; k0 += BK) {
        // ---- load + split A tile: BM x 16 ----
        #pragma unroll
        for (int it = 0; it < (BM * 4) / NT; it++) {
            int idx = tid + it * NT;
            int m = idx >> 2, kq = (idx & 3) << 2;
            float4 v = *(const float4*)(Ab + (size_t)m * lda + k0 + kq);
            float xs[4] = {v.x, v.y, v.z, v.w};
            #pragma unroll
            for (int j = 0; j < 4; j++) {
                unsigned hi, lo; tf32_split(xs[j], hi, lo);
                Ah[kq + j][m] = hi; Al[kq + j][m] = lo;
            }
        }
        // ---- load + split B tile: 16 x BN ----
        if (!transB) {
            #pragma unroll
            for (int it = 0; it < (BN * 4) / NT; it++) {
                int idx = tid + it * NT;
                int k = idx / (BN / 4), nq = (idx % (BN / 4)) << 2;
                float4 v = *(const float4*)(Bb + (size_t)(k0 + k) * ldb + n0 + nq);
                float xs[4] = {v.x, v.y, v.z, v.w};
                #pragma unroll
                for (int j = 0; j < 4; j++) {
                    unsigned hi, lo; tf32_split(xs[j], hi, lo);
                    Bh[k][nq + j] = hi; Bl[k][nq + j] = lo;
                }
            }
        } else {
            #pragma unroll
            for (int it = 0; it < (BN * 4) / NT; it++) {
                int idx = tid + it * NT;
                int n = idx >> 2, kq = (idx & 3) << 2;
                float4 v = *(const float4*)(Bb + (size_t)(n0 + n) * ldb + k0 + kq);
                float xs[4] = {v.x, v.y, v.z, v.w};
                #pragma unroll
                for (int j = 0; j < 4; j++) {
                    unsigned hi, lo; tf32_split(xs[j], hi, lo);
                    Bh[kq + j][n] = hi; Bl[kq + j][n] = lo;
                }
            }
        }
        __syncthreads();

        #pragma unroll
        for (int kk = 0; kk < BK; kk += 8) {
            unsigned ah[MF][4], al[MF][4], bh[NF][2], bl[NF][2];
            int c = kk + (lane & 3);
            #pragma unroll
            for (int mi = 0; mi < MF; mi++) {
                int r = wm * WM + mi * 16 + (lane >> 2);
                ah[mi][0] = Ah[c][r];     ah[mi][1] = Ah[c][r + 8];
                ah[mi][2] = Ah[c + 4][r]; ah[mi][3] = Ah[c + 4][r + 8];
                al[mi][0] = Al[c][r];     al[mi][1] = Al[c][r + 8];
                al[mi][2] = Al[c + 4][r]; al[mi][3] = Al[c + 4][r + 8];
            }
            #pragma unroll
            for (int ni = 0; ni < NF; ni++) {
                int n = wn * WN + ni * 8 + (lane >> 2);
                bh[ni][0] = Bh[c][n]; bh[ni][1] = Bh[c + 4][n];
                bl[ni][0] = Bl[c][n]; bl[ni][1] = Bl[c + 4][n];
            }
            #pragma unroll
            for (int mi = 0; mi < MF; mi++)
                #pragma unroll
                for (int ni = 0; ni < NF; ni++) {
                    MMA8(acc[mi][ni], ah[mi], bh[ni]);
                    MMA8(acc[mi][ni], ah[mi], bl[ni]);
                    MMA8(acc[mi][ni], al[mi], bh[ni]);
                }
        }
        __syncthreads();
    }

    // ---- epilogue ----
    float* Cb = Cx + (size_t)bz * sCb + (size_t)hz * sCh;
    #pragma unroll
    for (int mi = 0; mi < MF; mi++) {
        #pragma unroll
        for (int ni = 0; ni < NF; ni++) {
            int r0 = blockIdx.y * BM + wm * WM + mi * 16 + (lane >> 2);
            int cn = n0 + wn * WN + ni * 8 + 2 * (lane & 3);
            #pragma unroll
            for (int half = 0; half < 2; half++) {
                int r = r0 + half * 8;
                float v0 = acc[mi][ni][half * 2 + 0] * alpha;
                float v1 = acc[mi][ni][half * 2 + 1] * alpha;
                size_t off = (size_t)r * ldc + cn;
                if (epi == 0) {
                    *(float2*)(Cb + off) = make_float2(v0, v1);
                } else if (epi == 1) {
                    v0 = gelu_tanh(v0 + bias[cn]);
                    v1 = gelu_tanh(v1 + bias[cn + 1]);
                    *(float2*)(Cb + off) = make_float2(v0, v1);
                } else {
                    float2 old = *(float2*)(Cb + off);
                    old.x += (v0 + bias[cn]) * LSCALE;
                    old.y += (v1 + bias[cn + 1]) * LSCALE;
                    *(float2*)(Cb + off) = old;
                }
            }
        }
    }
}

// ---------------- fused mix_pre -> softmax -> mix_post ----------------
// block per (b, i): 384 threads = 12 warps, warp w owns head row g=w.
__global__ __launch_bounds__(384) void attn_mix_softmax(
    float* __restrict__ dots, const float* __restrict__ mp,
    const float* __restrict__ mq)
{
    __shared__ float S[NHEAD][SEQ];   // raw dots
    __shared__ float T[NHEAD][SEQ];   // mixed + softmaxed
    int tid = threadIdx.x, lane = tid & 31, g = tid >> 5;
    int b = blockIdx.x >> 9, i = blockIdx.x & 511;
    float* base = dots + ((size_t)(b * NHEAD) * SEQ + i) * SEQ;

    // cooperative load of all 12 head-rows (12*512 floats)
    #pragma unroll
    for (int it = 0; it < 4; it++) {
        int idx = tid + it * 384;              // 0..1535 float4s
        int h = idx >> 7, jq = (idx & 127) << 2;
        *(float4*)&S[h][jq] = *(const float4*)(base + (size_t)h * (SEQ * SEQ) + jq);
    }
    __syncthreads();

    // pre-softmax talking-heads mix into registers
    float mcol[NHEAD];
    #pragma unroll
    for (int h = 0; h < NHEAD; h++) mcol[h] = __ldg(&mp[h * NHEAD + g]);
    float v[16];
    float mx = -1e30f;
    #pragma unroll
    for (int k = 0; k < 16; k++) {
        int j = lane + k * 32;
        float a = 0.f;
        #pragma unroll
        for (int h = 0; h < NHEAD; h++) a += S[h][j] * mcol[h];
        v[k] = a; mx = fmaxf(mx, a);
    }
    #pragma unroll
    for (int off = 16; off > 0; off >>= 1)
        mx = fmaxf(mx, __shfl_xor_sync(0xffffffffu, mx, off));
    float s = 0.f;
    #pragma unroll
    for (int k = 0; k < 16; k++) { v[k] = __expf(v[k] - mx); s += v[k]; }
    #pragma unroll
    for (int off = 16; off > 0; off >>= 1)
        s += __shfl_xor_sync(0xffffffffu, s, off);
    float inv = 1.0f / s;
    #pragma unroll
    for (int k = 0; k < 16; k++) T[g][lane + k * 32] = v[k] * inv;
    __syncthreads();

    // post-softmax mix, write back
    float qcol[NHEAD];
    #pragma unroll
    for (int h = 0; h < NHEAD; h++) qcol[h] = __ldg(&mq[h * NHEAD + g]);
    #pragma unroll
    for (int k = 0; k < 16; k++) {
        int j = lane + k * 32;
        float a = 0.f;
        #pragma unroll
        for (int h = 0; h < NHEAD; h++) a += T[h][j] * qcol[h];
        base[(size_t)g * (SEQ * SEQ) + j] = a;
    }
}

// ---------------- launch ----------------
extern "C" void kernel_launch(void* const* d_in, const int* in_sizes, int n_in,
                              void* d_out, int out_size) {
    const float* x_in     = (const float*)d_in[0];
    const float* ln1      = (const float*)d_in[1];
    const float* Wq       = (const float*)d_in[2];
    const float* Wkv      = (const float*)d_in[3];
    const float* mix_pre  = (const float*)d_in[4];
    const float* mix_post = (const float*)d_in[5];
    const float* Wo       = (const float*)d_in[6];
    const float* bo       = (const float*)d_in[7];
    const float* ln2      = (const float*)d_in[8];
    const float* W1       = (const float*)d_in[9];
    const float* b1       = (const float*)d_in[10];
    const float* W2       = (const float*)d_in[11];
    const float* b2       = (const float*)d_in[12];

    float* X = (float*)d_out;

    float *h, *q, *kv, *dots, *o, *mlp;
    cudaGetSymbolAddress((void**)&h,    g_h);
    cudaGetSymbolAddress((void**)&q,    g_q);
    cudaGetSymbolAddress((void**)&kv,   g_kv);
    cudaGetSymbolAddress((void**)&dots, g_dots);
    cudaGetSymbolAddress((void**)&o,    g_o);
    cudaGetSymbolAddress((void**)&mlp,  g_mlp);

    cudaMemcpyAsync(X, x_in, (size_t)ROWS * DIM * sizeof(float),
                    cudaMemcpyDeviceToDevice);

    const long SSQ = (long)SEQ * SEQ;

    for (int d = 0; d < DEPTH; d++) {
        // ---- attention half ----
        ln_kernel<<<ROWS, 256>>>(X, ln1 + d * DIM, h);

        // q = h @ Wq
        tgemm<128,128,2,4><<<dim3(INNER/128, ROWS/128, 1), 256>>>(
            h, DIM, 0, 0,
            Wq + (size_t)d * DIM * INNER, INNER, 0, 0, 0,
            q, INNER, 0, 0, nullptr,
            ROWS, INNER, DIM, 1, 1.f, 0);
        // kv = h @ Wkv
        tgemm<128,128,2,4><<<dim3(2*INNER/128, ROWS/128, 1), 256>>>(
            h, DIM, 0, 0,
            Wkv + (size_t)d * DIM * 2 * INNER, 2*INNER, 0, 0, 0,
            kv, 2*INNER, 0, 0, nullptr,
            ROWS, 2*INNER, DIM, 1, 1.f, 0);

        // dots[b,h] = scale * q_bh @ k_bh^T
        tgemm<128,128,2,4><<<dim3(SEQ/128, SEQ/128, BATCH*NHEAD), 256>>>(
            q, INNER, (long)SEQ * INNER, DH,
            kv, 2*INNER, (long)SEQ * 2 * INNER, DH, 1,
            dots, SEQ, (long)NHEAD * SSQ, SSQ, nullptr,
            SEQ, SEQ, DH, NHEAD, ATT_SCALE, 0);

        attn_mix_softmax<<<BATCH * SEQ, 384>>>(dots, mix_pre + d * NHEAD * NHEAD,
                                               mix_post + d * NHEAD * NHEAD);

        // o[b,:,h*64+d] = attn_bh @ v_bh
        tgemm<128,64,4,2><<<dim3(1, SEQ/128, BATCH*NHEAD), 256>>>(
            dots, SEQ, (long)NHEAD * SSQ, SSQ,
            kv + INNER, 2*INNER, (long)SEQ * 2 * INNER, DH, 0,
            o, INNER, (long)SEQ * INNER, DH, nullptr,
            SEQ, DH, SEQ, NHEAD, 1.f, 0);

        // X += (o @ Wo + bo) * LS
        tgemm<128,128,2,4><<<dim3(DIM/128, ROWS/128, 1), 256>>>(
            o, INNER, 0, 0,
            Wo + (size_t)d * INNER * DIM, DIM, 0, 0, 0,
            X, DIM, 0, 0, bo + d * DIM,
            ROWS, DIM, INNER, 1, 1.f, 2);

        // ---- MLP half ----
        ln_kernel<<<ROWS, 256>>>(X, ln2 + d * DIM, h);

        tgemm<128,128,2,4><<<dim3(MLPDIM/128, ROWS/128, 1), 256>>>(
            h, DIM, 0, 0,
            W1 + (size_t)d * DIM * MLPDIM, MLPDIM, 0, 0, 0,
            mlp, MLPDIM, 0, 0, b1 + d * MLPDIM,
            ROWS, MLPDIM, DIM, 1, 1.f, 1);

        tgemm<128,128,2,4><<<dim3(DIM/128, ROWS/128, 1), 256>>>(
            mlp, MLPDIM, 0, 0,
            W2 + (size_t)d * MLPDIM * DIM, DIM, 0, 0, 0,
            X, DIM, 0, 0, b2 + d * DIM,
            ROWS, DIM, MLPDIM, 1, 1.f, 2);
    }
}

// round 3
// speedup vs baseline: 2.5712x; 2.1722x over previous
#include <cuda_runtime.h>
#include <cuda_bf16.h>
#include <math.h>

#define BATCH 8
#define SEQ 512
#define DIM 768
#define NHEAD 12
#define DH 64
#define INNER 768
#define MLPDIM 3072
#define DEPTH 4
#define ROWS (BATCH * SEQ)
#define LSCALE 0.1f
#define EPS 1e-5f
#define ATT_SCALE 0.125f
#define SSQ (SEQ * SEQ)

typedef __nv_bfloat16 bf16;

// ---------------- scratch (device globals) ----------------
__device__ bf16 g_h_hi [ROWS * DIM],    g_h_lo [ROWS * DIM];
__device__ bf16 g_q_hi [ROWS * INNER],  g_q_lo [ROWS * INNER];
__device__ bf16 g_k_hi [ROWS * INNER],  g_k_lo [ROWS * INNER];
__device__ bf16 g_vT_hi[ROWS * INNER],  g_vT_lo[ROWS * INNER];
__device__ float g_dots[BATCH * NHEAD * SSQ];
__device__ bf16 g_at_hi[BATCH * NHEAD * SSQ], g_at_lo[BATCH * NHEAD * SSQ];
__device__ bf16 g_o_hi [ROWS * INNER],  g_o_lo [ROWS * INNER];
__device__ bf16 g_m_hi [ROWS * MLPDIM], g_m_lo [ROWS * MLPDIM];
// transposed split weights, all layers
__device__ bf16 g_wqT_hi[DEPTH * DIM * INNER],  g_wqT_lo[DEPTH * DIM * INNER];
__device__ bf16 g_wkT_hi[DEPTH * DIM * INNER],  g_wkT_lo[DEPTH * DIM * INNER];
__device__ bf16 g_wvT_hi[DEPTH * DIM * INNER],  g_wvT_lo[DEPTH * DIM * INNER];
__device__ bf16 g_woT_hi[DEPTH * INNER * DIM],  g_woT_lo[DEPTH * INNER * DIM];
__device__ bf16 g_w1T_hi[DEPTH * DIM * MLPDIM], g_w1T_lo[DEPTH * DIM * MLPDIM];
__device__ bf16 g_w2T_hi[DEPTH * MLPDIM * DIM], g_w2T_lo[DEPTH * MLPDIM * DIM];

__device__ __forceinline__ float gelu_tanh(float x) {
    float x3 = x * x * x;
    return 0.5f * x * (1.0f + tanhf(0.7978845608028654f * (x + 0.044715f * x3)));
}
__device__ __forceinline__ void split2(float v, bf16& h, bf16& l) {
    h = __float2bfloat16(v);
    l = __float2bfloat16(v - __bfloat162float(h));
}

__device__ __forceinline__ void cp16(unsigned s, const void* g) {
    asm volatile("cp.async.cg.shared.global [%0], [%1], 16;\n" :: "r"(s), "l"(g));
}
__device__ __forceinline__ void cp_commit() {
    asm volatile("cp.async.commit_group;\n");
}
template<int N> __device__ __forceinline__ void cp_wait() {
    asm volatile("cp.async.wait_group %0;\n" :: "n"(N));
}
__device__ __forceinline__ void ldsm4(unsigned& r0, unsigned& r1, unsigned& r2,
                                      unsigned& r3, unsigned addr) {
    asm volatile("ldmatrix.sync.aligned.m8n8.x4.shared.b16 {%0,%1,%2,%3}, [%4];\n"
                 : "=r"(r0), "=r"(r1), "=r"(r2), "=r"(r3) : "r"(addr));
}
#define MMA16(d, a, b0, b1) \
    asm volatile("mma.sync.aligned.m16n8k16.row.col.f32.bf16.bf16.f32 " \
                 "{%0,%1,%2,%3},{%4,%5,%6,%7},{%8,%9},{%0,%1,%2,%3};\n" \
                 : "+f"(d[0]), "+f"(d[1]), "+f"(d[2]), "+f"(d[3])       \
                 : "r"(a[0]), "r"(a[1]), "r"(a[2]), "r"(a[3]), "r"(b0), "r"(b1))

// ---------------- transpose + split weights ----------------
// in[k][n] fp32 (ldin), out[n][k] bf16 hi/lo (ldout = K)
__global__ __launch_bounds__(256) void wsplit_t(const float* __restrict__ in, int ldin,
                                                int K, int N,
                                                bf16* __restrict__ oh, bf16* __restrict__ ol) {
    __shared__ float t[32][33];
    int tx = threadIdx.x, ty = threadIdx.y;
    int k0 = blockIdx.x * 32, n0 = blockIdx.y * 32;
    #pragma unroll
    for (int r = ty; r < 32; r += 8)
        t[r][tx] = in[(size_t)(k0 + r) * ldin + n0 + tx];
    __syncthreads();
    #pragma unroll
    for (int r = ty; r < 32; r += 8) {
        int n = n0 + r, k = k0 + tx;
        bf16 h, l; split2(t[tx][r], h, l);
        size_t idx = (size_t)n * K + k;
        oh[idx] = h; ol[idx] = l;
    }
}

// ---------------- LayerNorm -> split ----------------
__global__ __launch_bounds__(256) void ln_split(const float* __restrict__ x,
                                                const float* __restrict__ scale,
                                                bf16* __restrict__ oh, bf16* __restrict__ ol) {
    int row = blockIdx.x;
    const float* xr = x + (size_t)row * DIM;
    int tid = threadIdx.x;
    float s = 0.f, s2 = 0.f;
    for (int c = tid; c < DIM; c += 256) { float v = xr[c]; s += v; s2 += v * v; }
    __shared__ float rs[256], rs2[256];
    rs[tid] = s; rs2[tid] = s2;
    __syncthreads();
    for (int off = 128; off > 0; off >>= 1) {
        if (tid < off) { rs[tid] += rs[tid + off]; rs2[tid] += rs2[tid + off]; }
        __syncthreads();
    }
    float mu = rs[0] * (1.0f / DIM);
    float var = rs2[0] * (1.0f / DIM) - mu * mu;
    float rstd = rsqrtf(var + EPS);
    for (int c = tid; c < DIM; c += 256) {
        float v = (xr[c] - mu) * rstd * scale[c];
        bf16 h, l; split2(v, h, l);
        size_t idx = (size_t)row * DIM + c;
        oh[idx] = h; ol[idx] = l;
    }
}

// ---------------- fused mix_pre -> softmax -> mix_post -> split ----------------
__global__ __launch_bounds__(384) void attn_mix_softmax(
    const float* __restrict__ dots, const float* __restrict__ mp,
    const float* __restrict__ mq, bf16* __restrict__ ah, bf16* __restrict__ al)
{
    __shared__ float S[NHEAD][SEQ];
    __shared__ float T[NHEAD][SEQ];
    int tid = threadIdx.x, lane = tid & 31, g = tid >> 5;
    int b = blockIdx.x >> 9, i = blockIdx.x & 511;
    const float* base = dots + ((size_t)(b * NHEAD) * SEQ + i) * SEQ;

    #pragma unroll
    for (int it = 0; it < 4; it++) {
        int idx = tid + it * 384;
        int h = idx >> 7, jq = (idx & 127) << 2;
        *(float4*)&S[h][jq] = *(const float4*)(base + (size_t)h * SSQ + jq);
    }
    __syncthreads();

    float mcol[NHEAD];
    #pragma unroll
    for (int h = 0; h < NHEAD; h++) mcol[h] = __ldg(&mp[h * NHEAD + g]);
    float v[16];
    float mx = -1e30f;
    #pragma unroll
    for (int k = 0; k < 16; k++) {
        int j = lane + k * 32;
        float a = 0.f;
        #pragma unroll
        for (int h = 0; h < NHEAD; h++) a += S[h][j] * mcol[h];
        v[k] = a; mx = fmaxf(mx, a);
    }
    #pragma unroll
    for (int off = 16; off > 0; off >>= 1)
        mx = fmaxf(mx, __shfl_xor_sync(0xffffffffu, mx, off));
    float s = 0.f;
    #pragma unroll
    for (int k = 0; k < 16; k++) { v[k] = __expf(v[k] - mx); s += v[k]; }
    #pragma unroll
    for (int off = 16; off > 0; off >>= 1)
        s += __shfl_xor_sync(0xffffffffu, s, off);
    float inv = 1.0f / s;
    #pragma unroll
    for (int k = 0; k < 16; k++) T[g][lane + k * 32] = v[k] * inv;
    __syncthreads();

    float qcol[NHEAD];
    #pragma unroll
    for (int h = 0; h < NHEAD; h++) qcol[h] = __ldg(&mq[h * NHEAD + g]);
    size_t ob = ((size_t)((b * NHEAD + g) * SEQ) + i) * SEQ;
    #pragma unroll
    for (int k = 0; k < 16; k++) {
        int j = lane + k * 32;
        float a = 0.f;
        #pragma unroll
        for (int h = 0; h < NHEAD; h++) a += T[h][j] * qcol[h];
        bf16 hh, ll; split2(a, hh, ll);
        ah[ob + j] = hh; al[ob + j] = ll;
    }
}

// ---------------- bf16 split tensor-core GEMM, cp.async 3-stage pipeline ----
// A[m][k] split bf16 (hi/lo), B[n][k] split bf16, batched over z = bz*nH+hz.
// epi: 0 C=f32 alpha*acc   1 split-store   2 X += (acc+bias)*LS (f32)
//      3 split-store transposed to vT      4 gelu(acc+bias) split-store
template<int BM, int BN, int WARPS_M, int WARPS_N>
__global__ __launch_bounds__(256) void tgemm_bf(
    const bf16* __restrict__ Ahp, const bf16* __restrict__ Alp, int lda, long sAb, long sAh,
    const bf16* __restrict__ Bhp, const bf16* __restrict__ Blp, int ldb, long sBb, long sBh,
    float* __restrict__ Cf, bf16* __restrict__ Chi, bf16* __restrict__ Clo,
    int ldc, long sCb, long sCh,
    const float* __restrict__ bias,
    int M, int N, int K, int nH, float alpha, int epi)
{
    constexpr int BK = 32;            // bf16 elements per k-tile
    constexpr int STAGES = 3;
    constexpr int RB = 80;            // bytes per smem row (64 data + 16 pad)
    constexpr int WM = BM / WARPS_M;
    constexpr int WN = BN / WARPS_N;
    constexpr int MF = WM / 16;
    constexpr int NF = WN / 8;
    constexpr int NF2 = NF / 2;
    constexpr int NT = 256;
    constexpr int STAGE_BYTES = (2 * BM + 2 * BN) * RB;
    constexpr unsigned OFF_AL = BM * RB;
    constexpr unsigned OFF_BH = 2 * BM * RB;
    constexpr unsigned OFF_BL = 2 * BM * RB + BN * RB;

    extern __shared__ __align__(16) char dsmem[];
    unsigned smemBase = (unsigned)__cvta_generic_to_shared(dsmem);

    int tid = threadIdx.x, lane = tid & 31, warp = tid >> 5;
    int wm = warp / WARPS_N, wn = warp % WARPS_N;
    int bz = blockIdx.z / nH, hz = blockIdx.z % nH;
    int row0 = blockIdx.y * BM, n0 = blockIdx.x * BN;

    const bf16* Ah = Ahp + (size_t)bz * sAb + (size_t)hz * sAh + (size_t)row0 * lda;
    const bf16* Al = Alp + (size_t)bz * sAb + (size_t)hz * sAh + (size_t)row0 * lda;
    const bf16* Bh = Bhp + (size_t)bz * sBb + (size_t)hz * sBh + (size_t)n0 * ldb;
    const bf16* Bl = Blp + (size_t)bz * sBb + (size_t)hz * sBh + (size_t)n0 * ldb;

    const int KT = K / BK;
    constexpr int CH_A = BM * 4, CH_B = BN * 4;
    constexpr int TOT = 2 * CH_A + 2 * CH_B;

    auto load_stage = [&](int t) {
        unsigned sb = smemBase + (unsigned)((t % STAGES) * STAGE_BYTES);
        int k0 = t * BK;
        #pragma unroll
        for (int c = tid; c < TOT; c += NT) {
            int cc = c; const bf16* gp; unsigned soff;
            if (cc < CH_A) {
                int r = cc >> 2, o = cc & 3;
                gp = Ah + (size_t)r * lda + k0 + o * 8;
                soff = (unsigned)(r * RB + o * 16);
            } else if (cc < 2 * CH_A) {
                cc -= CH_A; int r = cc >> 2, o = cc & 3;
                gp = Al + (size_t)r * lda + k0 + o * 8;
                soff = OFF_AL + (unsigned)(r * RB + o * 16);
            } else if (cc < 2 * CH_A + CH_B) {
                cc -= 2 * CH_A; int r = cc >> 2, o = cc & 3;
                gp = Bh + (size_t)r * ldb + k0 + o * 8;
                soff = OFF_BH + (unsigned)(r * RB + o * 16);
            } else {
                cc -= 2 * CH_A + CH_B; int r = cc >> 2, o = cc & 3;
                gp = Bl + (size_t)r * ldb + k0 + o * 8;
                soff = OFF_BL + (unsigned)(r * RB + o * 16);
            }
            cp16(sb + soff, gp);
        }
    };

    float acc[MF][NF][4] = {};

    // prologue
    #pragma unroll
    for (int s = 0; s < STAGES - 1; s++) {
        if (s < KT) { load_stage(s); cp_commit(); }
    }

    int arow = lane & 15;
    int acol = (lane >> 4) << 4;
    int nrow = (lane & 7) | ((lane & 16) >> 1);
    int ncol = (lane & 8) ? 16 : 0;

    for (int t = 0; t < KT; t++) {
        if (t + STAGES - 1 < KT) cp_wait<STAGES - 2>(); else cp_wait<0>();
        __syncthreads();
        if (t + STAGES - 1 < KT) { load_stage(t + STAGES - 1); cp_commit(); }

        unsigned sb = smemBase + (unsigned)((t % STAGES) * STAGE_BYTES);
        #pragma unroll
        for (int kk = 0; kk < 2; kk++) {
            unsigned ah[MF][4], al[MF][4], bh[NF2][4], bl[NF2][4];
            #pragma unroll
            for (int mi = 0; mi < MF; mi++) {
                unsigned base = sb + (unsigned)((wm * WM + mi * 16 + arow) * RB + kk * 32 + acol);
                ldsm4(ah[mi][0], ah[mi][1], ah[mi][2], ah[mi][3], base);
                ldsm4(al[mi][0], al[mi][1], al[mi][2], al[mi][3], base + OFF_AL);
            }
            #pragma unroll
            for (int j = 0; j < NF2; j++) {
                unsigned base = sb + OFF_BH + (unsigned)((wn * WN + j * 16 + nrow) * RB + kk * 32 + ncol);
                ldsm4(bh[j][0], bh[j][1], bh[j][2], bh[j][3], base);
                ldsm4(bl[j][0], bl[j][1], bl[j][2], bl[j][3], base + (OFF_BL - OFF_BH));
            }
            #pragma unroll
            for (int mi = 0; mi < MF; mi++)
                #pragma unroll
                for (int ni = 0; ni < NF; ni++) {
                    int j = ni >> 1, o = (ni & 1) * 2;
                    MMA16(acc[mi][ni], ah[mi], bh[j][o], bh[j][o + 1]);
                    MMA16(acc[mi][ni], ah[mi], bl[j][o], bl[j][o + 1]);
                    MMA16(acc[mi][ni], al[mi], bh[j][o], bh[j][o + 1]);
                }
        }
    }

    // ---- epilogue ----
    float* Cfb = Cf ? Cf + (size_t)bz * sCb + (size_t)hz * sCh : nullptr;
    bf16* Chb = Chi ? Chi + (size_t)bz * sCb + (size_t)hz * sCh : nullptr;
    bf16* Clb = Clo ? Clo + (size_t)bz * sCb + (size_t)hz * sCh : nullptr;

    #pragma unroll
    for (int mi = 0; mi < MF; mi++) {
        #pragma unroll
        for (int ni = 0; ni < NF; ni++) {
            int r0 = row0 + wm * WM + mi * 16 + (lane >> 2);
            int cn = n0 + wn * WN + ni * 8 + 2 * (lane & 3);
            #pragma unroll
            for (int half = 0; half < 2; half++) {
                int r = r0 + half * 8;
                float v0 = acc[mi][ni][half * 2 + 0] * alpha;
                float v1 = acc[mi][ni][half * 2 + 1] * alpha;
                if (epi == 0) {
                    *(float2*)(Cfb + (size_t)r * ldc + cn) = make_float2(v0, v1);
                } else if (epi == 1) {
                    size_t off = (size_t)r * ldc + cn;
                    bf16 h0, l0, h1, l1; split2(v0, h0, l0); split2(v1, h1, l1);
                    __nv_bfloat162 ph; ph.x = h0; ph.y = h1;
                    __nv_bfloat162 pl; pl.x = l0; pl.y = l1;
                    *(__nv_bfloat162*)(Chb + off) = ph;
                    *(__nv_bfloat162*)(Clb + off) = pl;
                } else if (epi == 2) {
                    size_t off = (size_t)r * ldc + cn;
                    float2 old = *(float2*)(Cfb + off);
                    old.x += (v0 + bias[cn]) * LSCALE;
                    old.y += (v1 + bias[cn + 1]) * LSCALE;
                    *(float2*)(Cfb + off) = old;
                } else if (epi == 3) {
                    // v proj: row = b*512+i, col cn = h*64+d -> vT[(b*768+cn)*512 + i]
                    int bb = r >> 9, ii = r & 511;
                    size_t idx = ((size_t)bb * 768 + cn) * 512 + ii;
                    bf16 h0, l0, h1, l1; split2(v0, h0, l0); split2(v1, h1, l1);
                    Chb[idx] = h0; Clb[idx] = l0;
                    Chb[idx + 512] = h1; Clb[idx + 512] = l1;
                } else {
                    size_t off = (size_t)r * ldc + cn;
                    float t0 = gelu_tanh(v0 + bias[cn]);
                    float t1 = gelu_tanh(v1 + bias[cn + 1]);
                    bf16 h0, l0, h1, l1; split2(t0, h0, l0); split2(t1, h1, l1);
                    __nv_bfloat162 ph; ph.x = h0; ph.y = h1;
                    __nv_bfloat162 pl; pl.x = l0; pl.y = l1;
                    *(__nv_bfloat162*)(Chb + off) = ph;
                    *(__nv_bfloat162*)(Clb + off) = pl;
                }
            }
        }
    }
}

// ---------------- launch ----------------
extern "C" void kernel_launch(void* const* d_in, const int* in_sizes, int n_in,
                              void* d_out, int out_size) {
    const float* x_in     = (const float*)d_in[0];
    const float* ln1      = (const float*)d_in[1];
    const float* Wq       = (const float*)d_in[2];
    const float* Wkv      = (const float*)d_in[3];
    const float* mix_pre  = (const float*)d_in[4];
    const float* mix_post = (const float*)d_in[5];
    const float* Wo       = (const float*)d_in[6];
    const float* bo       = (const float*)d_in[7];
    const float* ln2      = (const float*)d_in[8];
    const float* W1       = (const float*)d_in[9];
    const float* b1       = (const float*)d_in[10];
    const float* W2       = (const float*)d_in[11];
    const float* b2       = (const float*)d_in[12];

    float* X = (float*)d_out;

    bf16 *h_hi, *h_lo, *q_hi, *q_lo, *k_hi, *k_lo, *vT_hi, *vT_lo;
    bf16 *at_hi, *at_lo, *o_hi, *o_lo, *m_hi, *m_lo;
    bf16 *wqT_hi, *wqT_lo, *wkT_hi, *wkT_lo, *wvT_hi, *wvT_lo;
    bf16 *woT_hi, *woT_lo, *w1T_hi, *w1T_lo, *w2T_hi, *w2T_lo;
    float* dots;
    cudaGetSymbolAddress((void**)&h_hi, g_h_hi);   cudaGetSymbolAddress((void**)&h_lo, g_h_lo);
    cudaGetSymbolAddress((void**)&q_hi, g_q_hi);   cudaGetSymbolAddress((void**)&q_lo, g_q_lo);
    cudaGetSymbolAddress((void**)&k_hi, g_k_hi);   cudaGetSymbolAddress((void**)&k_lo, g_k_lo);
    cudaGetSymbolAddress((void**)&vT_hi, g_vT_hi); cudaGetSymbolAddress((void**)&vT_lo, g_vT_lo);
    cudaGetSymbolAddress((void**)&at_hi, g_at_hi); cudaGetSymbolAddress((void**)&at_lo, g_at_lo);
    cudaGetSymbolAddress((void**)&o_hi, g_o_hi);   cudaGetSymbolAddress((void**)&o_lo, g_o_lo);
    cudaGetSymbolAddress((void**)&m_hi, g_m_hi);   cudaGetSymbolAddress((void**)&m_lo, g_m_lo);
    cudaGetSymbolAddress((void**)&wqT_hi, g_wqT_hi); cudaGetSymbolAddress((void**)&wqT_lo, g_wqT_lo);
    cudaGetSymbolAddress((void**)&wkT_hi, g_wkT_hi); cudaGetSymbolAddress((void**)&wkT_lo, g_wkT_lo);
    cudaGetSymbolAddress((void**)&wvT_hi, g_wvT_hi); cudaGetSymbolAddress((void**)&wvT_lo, g_wvT_lo);
    cudaGetSymbolAddress((void**)&woT_hi, g_woT_hi); cudaGetSymbolAddress((void**)&woT_lo, g_woT_lo);
    cudaGetSymbolAddress((void**)&w1T_hi, g_w1T_hi); cudaGetSymbolAddress((void**)&w1T_lo, g_w1T_lo);
    cudaGetSymbolAddress((void**)&w2T_hi, g_w2T_hi); cudaGetSymbolAddress((void**)&w2T_lo, g_w2T_lo);
    cudaGetSymbolAddress((void**)&dots, g_dots);

    const int SM128 = (2 * 128 + 2 * 128) * 80 * 3;   // 122880
    const int SM64  = (2 * 128 + 2 * 64) * 80 * 3;    //  92160
    cudaFuncSetAttribute((const void*)tgemm_bf<128, 128, 2, 4>,
                         cudaFuncAttributeMaxDynamicSharedMemorySize, SM128);
    cudaFuncSetAttribute((const void*)tgemm_bf<128, 64, 4, 2>,
                         cudaFuncAttributeMaxDynamicSharedMemorySize, SM64);

    cudaMemcpyAsync(X, x_in, (size_t)ROWS * DIM * sizeof(float),
                    cudaMemcpyDeviceToDevice);

    // ---- weight transpose+split (all layers) ----
    dim3 tb(32, 8);
    for (int d = 0; d < DEPTH; d++) {
        size_t wo768 = (size_t)d * DIM * INNER;
        wsplit_t<<<dim3(DIM / 32, INNER / 32), tb>>>(Wq + wo768, INNER, DIM, INNER,
                                                     wqT_hi + wo768, wqT_lo + wo768);
        wsplit_t<<<dim3(DIM / 32, INNER / 32), tb>>>(Wkv + (size_t)d * DIM * 2 * INNER,
                                                     2 * INNER, DIM, INNER,
                                                     wkT_hi + wo768, wkT_lo + wo768);
        wsplit_t<<<dim3(DIM / 32, INNER / 32), tb>>>(Wkv + (size_t)d * DIM * 2 * INNER + INNER,
                                                     2 * INNER, DIM, INNER,
                                                     wvT_hi + wo768, wvT_lo + wo768);
        wsplit_t<<<dim3(INNER / 32, DIM / 32), tb>>>(Wo + wo768, DIM, INNER, DIM,
                                                     woT_hi + wo768, woT_lo + wo768);
        size_t w1o = (size_t)d * DIM * MLPDIM;
        wsplit_t<<<dim3(DIM / 32, MLPDIM / 32), tb>>>(W1 + w1o, MLPDIM, DIM, MLPDIM,
                                                      w1T_hi + w1o, w1T_lo + w1o);
        wsplit_t<<<dim3(MLPDIM / 32, DIM / 32), tb>>>(W2 + w1o, DIM, MLPDIM, DIM,
                                                      w2T_hi + w1o, w2T_lo + w1o);
    }

    for (int d = 0; d < DEPTH; d++) {
        size_t wo768 = (size_t)d * DIM * INNER;
        size_t w1o = (size_t)d * DIM * MLPDIM;

        // ---- attention half ----
        ln_split<<<ROWS, 256>>>(X, ln1 + d * DIM, h_hi, h_lo);

        tgemm_bf<128, 128, 2, 4><<<dim3(INNER / 128, ROWS / 128, 1), 256, SM128>>>(
            h_hi, h_lo, DIM, 0, 0,
            wqT_hi + wo768, wqT_lo + wo768, DIM, 0, 0,
            nullptr, q_hi, q_lo, INNER, 0, 0, nullptr,
            ROWS, INNER, DIM, 1, 1.f, 1);
        tgemm_bf<128, 128, 2, 4><<<dim3(INNER / 128, ROWS / 128, 1), 256, SM128>>>(
            h_hi, h_lo, DIM, 0, 0,
            wkT_hi + wo768, wkT_lo + wo768, DIM, 0, 0,
            nullptr, k_hi, k_lo, INNER, 0, 0, nullptr,
            ROWS, INNER, DIM, 1, 1.f, 1);
        tgemm_bf<128, 128, 2, 4><<<dim3(INNER / 128, ROWS / 128, 1), 256, SM128>>>(
            h_hi, h_lo, DIM, 0, 0,
            wvT_hi + wo768, wvT_lo + wo768, DIM, 0, 0,
            nullptr, vT_hi, vT_lo, 0, 0, 0, nullptr,
            ROWS, INNER, DIM, 1, 1.f, 3);

        // dots = scale * q @ k^T  per (b,h)
        tgemm_bf<128, 128, 2, 4><<<dim3(SEQ / 128, SEQ / 128, BATCH * NHEAD), 256, SM128>>>(
            q_hi, q_lo, INNER, (long)SEQ * INNER, DH,
            k_hi, k_lo, INNER, (long)SEQ * INNER, DH,
            dots, nullptr, nullptr, SEQ, (long)NHEAD * SSQ, (long)SSQ, nullptr,
            SEQ, SEQ, DH, NHEAD, ATT_SCALE, 0);

        attn_mix_softmax<<<BATCH * SEQ, 384>>>(dots, mix_pre + d * NHEAD * NHEAD,
                                               mix_post + d * NHEAD * NHEAD, at_hi, at_lo);

        // o = attn @ v   (v pre-transposed)
        tgemm_bf<128, 64, 4, 2><<<dim3(1, SEQ / 128, BATCH * NHEAD), 256, SM64>>>(
            at_hi, at_lo, SEQ, (long)NHEAD * SSQ, (long)SSQ,
            vT_hi, vT_lo, SEQ, (long)NHEAD * DH * SEQ, (long)DH * SEQ,
            nullptr, o_hi, o_lo, INNER, (long)SEQ * INNER, DH, nullptr,
            SEQ, DH, SEQ, NHEAD, 1.f, 1);

        // X += (o @ Wo + bo) * LS
        tgemm_bf<128, 128, 2, 4><<<dim3(DIM / 128, ROWS / 128, 1), 256, SM128>>>(
            o_hi, o_lo, INNER, 0, 0,
            woT_hi + wo768, woT_lo + wo768, INNER, 0, 0,
            X, nullptr, nullptr, DIM, 0, 0, bo + d * DIM,
            ROWS, DIM, INNER, 1, 1.f, 2);

        // ---- MLP half ----
        ln_split<<<ROWS, 256>>>(X, ln2 + d * DIM, h_hi, h_lo);

        tgemm_bf<128, 128, 2, 4><<<dim3(MLPDIM / 128, ROWS / 128, 1), 256, SM128>>>(
            h_hi, h_lo, DIM, 0, 0,
            w1T_hi + w1o, w1T_lo + w1o, DIM, 0, 0,
            nullptr, m_hi, m_lo, MLPDIM, 0, 0, b1 + d * MLPDIM,
            ROWS, MLPDIM, DIM, 1, 1.f, 4);

        tgemm_bf<128, 128, 2, 4><<<dim3(DIM / 128, ROWS / 128, 1), 256, SM128>>>(
            m_hi, m_lo, MLPDIM, 0, 0,
            w2T_hi + w1o, w2T_lo + w1o, MLPDIM, 0, 0,
            X, nullptr, nullptr, DIM, 0, 0, b2 + d * DIM,
            ROWS, DIM, MLPDIM, 1, 1.f, 2);
    }
}

// round 4
// speedup vs baseline: 2.5779x; 1.0026x over previous
#include <cuda_runtime.h>
#include <cuda_bf16.h>
#include <math.h>

#define BATCH 8
#define SEQ 512
#define DIM 768
#define NHEAD 12
#define DH 64
#define INNER 768
#define MLPDIM 3072
#define DEPTH 4
#define ROWS (BATCH * SEQ)
#define LSCALE 0.1f
#define EPS 1e-5f
#define ATT_SCALE 0.125f
#define SSQ (SEQ * SEQ)

typedef __nv_bfloat16 bf16;

// ---------------- scratch (device globals) ----------------
__device__ bf16 g_h_hi [ROWS * DIM],    g_h_lo [ROWS * DIM];
__device__ bf16 g_q_hi [ROWS * INNER],  g_q_lo [ROWS * INNER];
__device__ bf16 g_k_hi [ROWS * INNER],  g_k_lo [ROWS * INNER];
__device__ bf16 g_vT_hi[ROWS * INNER],  g_vT_lo[ROWS * INNER];
__device__ float g_dots[BATCH * NHEAD * SSQ];
__device__ bf16 g_at_hi[BATCH * NHEAD * SSQ], g_at_lo[BATCH * NHEAD * SSQ];
__device__ bf16 g_o_hi [ROWS * INNER],  g_o_lo [ROWS * INNER];
__device__ bf16 g_m_hi [ROWS * MLPDIM], g_m_lo [ROWS * MLPDIM];
// transposed split weights, all layers
__device__ bf16 g_wqT_hi[DEPTH * DIM * INNER],  g_wqT_lo[DEPTH * DIM * INNER];
__device__ bf16 g_wkT_hi[DEPTH * DIM * INNER],  g_wkT_lo[DEPTH * DIM * INNER];
__device__ bf16 g_wvT_hi[DEPTH * DIM * INNER],  g_wvT_lo[DEPTH * DIM * INNER];
__device__ bf16 g_woT_hi[DEPTH * INNER * DIM],  g_woT_lo[DEPTH * INNER * DIM];
__device__ bf16 g_w1T_hi[DEPTH * DIM * MLPDIM], g_w1T_lo[DEPTH * DIM * MLPDIM];
__device__ bf16 g_w2T_hi[DEPTH * MLPDIM * DIM], g_w2T_lo[DEPTH * MLPDIM * DIM];

__device__ __forceinline__ float gelu_tanh(float x) {
    float x3 = x * x * x;
    return 0.5f * x * (1.0f + tanhf(0.7978845608028654f * (x + 0.044715f * x3)));
}
__device__ __forceinline__ void split2(float v, bf16& h, bf16& l) {
    h = __float2bfloat16(v);
    l = __float2bfloat16(v - __bfloat162float(h));
}

__device__ __forceinline__ void cp16(unsigned s, const void* g) {
    asm volatile("cp.async.cg.shared.global [%0], [%1], 16;\n" :: "r"(s), "l"(g));
}
__device__ __forceinline__ void cp_commit() {
    asm volatile("cp.async.commit_group;\n");
}
template<int N> __device__ __forceinline__ void cp_wait() {
    asm volatile("cp.async.wait_group %0;\n" :: "n"(N));
}
__device__ __forceinline__ void ldsm4(unsigned& r0, unsigned& r1, unsigned& r2,
                                      unsigned& r3, unsigned addr) {
    asm volatile("ldmatrix.sync.aligned.m8n8.x4.shared.b16 {%0,%1,%2,%3}, [%4];\n"
                 : "=r"(r0), "=r"(r1), "=r"(r2), "=r"(r3) : "r"(addr));
}
#define MMA16(d, a, b0, b1) \
    asm volatile("mma.sync.aligned.m16n8k16.row.col.f32.bf16.bf16.f32 " \
                 "{%0,%1,%2,%3},{%4,%5,%6,%7},{%8,%9},{%0,%1,%2,%3};\n" \
                 : "+f"(d[0]), "+f"(d[1]), "+f"(d[2]), "+f"(d[3])       \
                 : "r"(a[0]), "r"(a[1]), "r"(a[2]), "r"(a[3]), "r"(b0), "r"(b1))

// ---------------- transpose + split weights ----------------
// in[k][n] fp32 (ldin), out[n][k] bf16 hi/lo (ldout = K)
__global__ __launch_bounds__(256) void wsplit_t(const float* __restrict__ in, int ldin,
                                                int K, int N,
                                                bf16* __restrict__ oh, bf16* __restrict__ ol) {
    __shared__ float t[32][33];
    int tx = threadIdx.x, ty = threadIdx.y;
    int k0 = blockIdx.x * 32, n0 = blockIdx.y * 32;
    #pragma unroll
    for (int r = ty; r < 32; r += 8)
        t[r][tx] = in[(size_t)(k0 + r) * ldin + n0 + tx];
    __syncthreads();
    #pragma unroll
    for (int r = ty; r < 32; r += 8) {
        int n = n0 + r, k = k0 + tx;
        bf16 h, l; split2(t[tx][r], h, l);
        size_t idx = (size_t)n * K + k;
        oh[idx] = h; ol[idx] = l;
    }
}

// ---------------- LayerNorm -> split ----------------
__global__ __launch_bounds__(256) void ln_split(const float* __restrict__ x,
                                                const float* __restrict__ scale,
                                                bf16* __restrict__ oh, bf16* __restrict__ ol) {
    int row = blockIdx.x;
    const float* xr = x + (size_t)row * DIM;
    int tid = threadIdx.x;
    float s = 0.f, s2 = 0.f;
    for (int c = tid; c < DIM; c += 256) { float v = xr[c]; s += v; s2 += v * v; }
    __shared__ float rs[256], rs2[256];
    rs[tid] = s; rs2[tid] = s2;
    __syncthreads();
    for (int off = 128; off > 0; off >>= 1) {
        if (tid < off) { rs[tid] += rs[tid + off]; rs2[tid] += rs2[tid + off]; }
        __syncthreads();
    }
    float mu = rs[0] * (1.0f / DIM);
    float var = rs2[0] * (1.0f / DIM) - mu * mu;
    float rstd = rsqrtf(var + EPS);
    for (int c = tid; c < DIM; c += 256) {
        float v = (xr[c] - mu) * rstd * scale[c];
        bf16 h, l; split2(v, h, l);
        size_t idx = (size_t)row * DIM + c;
        oh[idx] = h; ol[idx] = l;
    }
}

// ---------------- fused mix_pre -> softmax -> mix_post -> split ----------------
__global__ __launch_bounds__(384) void attn_mix_softmax(
    const float* __restrict__ dots, const float* __restrict__ mp,
    const float* __restrict__ mq, bf16* __restrict__ ah, bf16* __restrict__ al)
{
    __shared__ float S[NHEAD][SEQ];
    __shared__ float T[NHEAD][SEQ];
    int tid = threadIdx.x, lane = tid & 31, g = tid >> 5;
    int b = blockIdx.x >> 9, i = blockIdx.x & 511;
    const float* base = dots + ((size_t)(b * NHEAD) * SEQ + i) * SEQ;

    #pragma unroll
    for (int it = 0; it < 4; it++) {
        int idx = tid + it * 384;
        int h = idx >> 7, jq = (idx & 127) << 2;
        *(float4*)&S[h][jq] = *(const float4*)(base + (size_t)h * SSQ + jq);
    }
    __syncthreads();

    float mcol[NHEAD];
    #pragma unroll
    for (int h = 0; h < NHEAD; h++) mcol[h] = __ldg(&mp[h * NHEAD + g]);
    float v[16];
    float mx = -1e30f;
    #pragma unroll
    for (int k = 0; k < 16; k++) {
        int j = lane + k * 32;
        float a = 0.f;
        #pragma unroll
        for (int h = 0; h < NHEAD; h++) a += S[h][j] * mcol[h];
        v[k] = a; mx = fmaxf(mx, a);
    }
    #pragma unroll
    for (int off = 16; off > 0; off >>= 1)
        mx = fmaxf(mx, __shfl_xor_sync(0xffffffffu, mx, off));
    float s = 0.f;
    #pragma unroll
    for (int k = 0; k < 16; k++) { v[k] = __expf(v[k] - mx); s += v[k]; }
    #pragma unroll
    for (int off = 16; off > 0; off >>= 1)
        s += __shfl_xor_sync(0xffffffffu, s, off);
    float inv = 1.0f / s;
    #pragma unroll
    for (int k = 0; k < 16; k++) T[g][lane + k * 32] = v[k] * inv;
    __syncthreads();

    float qcol[NHEAD];
    #pragma unroll
    for (int h = 0; h < NHEAD; h++) qcol[h] = __ldg(&mq[h * NHEAD + g]);
    size_t ob = ((size_t)((b * NHEAD + g) * SEQ) + i) * SEQ;
    #pragma unroll
    for (int k = 0; k < 16; k++) {
        int j = lane + k * 32;
        float a = 0.f;
        #pragma unroll
        for (int h = 0; h < NHEAD; h++) a += T[h][j] * qcol[h];
        bf16 hh, ll; split2(a, hh, ll);
        ah[ob + j] = hh; al[ob + j] = ll;
    }
}

// ---------------- bf16 split tensor-core GEMM, cp.async 3-stage pipeline ----
// A[m][k] split bf16 (hi/lo), B[n][k] split bf16, batched over z = bz*nH+hz.
// epi: 0 C=f32 alpha*acc   1 split-store   2 X += (acc+bias)*LS (f32)
//      3 split-store transposed to vT      4 gelu(acc+bias) split-store
template<int BM, int BN, int WARPS_M, int WARPS_N>
__global__ __launch_bounds__(256) void tgemm_bf(
    const bf16* __restrict__ Ahp, const bf16* __restrict__ Alp, int lda, long sAb, long sAh,
    const bf16* __restrict__ Bhp, const bf16* __restrict__ Blp, int ldb, long sBb, long sBh,
    float* __restrict__ Cf, bf16* __restrict__ Chi, bf16* __restrict__ Clo,
    int ldc, long sCb, long sCh,
    const float* __restrict__ bias,
    int M, int N, int K, int nH, float alpha, int epi)
{
    constexpr int BK = 32;            // bf16 elements per k-tile
    constexpr int STAGES = 3;
    constexpr int RB = 80;            // bytes per smem row (64 data + 16 pad)
    constexpr int WM = BM / WARPS_M;
    constexpr int WN = BN / WARPS_N;
    constexpr int MF = WM / 16;
    constexpr int NF = WN / 8;
    constexpr int NF2 = NF / 2;
    constexpr int NT = 256;
    constexpr int STAGE_BYTES = (2 * BM + 2 * BN) * RB;
    constexpr unsigned OFF_AL = BM * RB;
    constexpr unsigned OFF_BH = 2 * BM * RB;
    constexpr unsigned OFF_BL = 2 * BM * RB + BN * RB;

    extern __shared__ __align__(16) char dsmem[];
    unsigned smemBase = (unsigned)__cvta_generic_to_shared(dsmem);

    int tid = threadIdx.x, lane = tid & 31, warp = tid >> 5;
    int wm = warp / WARPS_N, wn = warp % WARPS_N;
    int bz = blockIdx.z / nH, hz = blockIdx.z % nH;
    int row0 = blockIdx.y * BM, n0 = blockIdx.x * BN;

    const bf16* Ah = Ahp + (size_t)bz * sAb + (size_t)hz * sAh + (size_t)row0 * lda;
    const bf16* Al = Alp + (size_t)bz * sAb + (size_t)hz * sAh + (size_t)row0 * lda;
    const bf16* Bh = Bhp + (size_t)bz * sBb + (size_t)hz * sBh + (size_t)n0 * ldb;
    const bf16* Bl = Blp + (size_t)bz * sBb + (size_t)hz * sBh + (size_t)n0 * ldb;

    const int KT = K / BK;
    constexpr int CH_A = BM * 4, CH_B = BN * 4;
    constexpr int TOT = 2 * CH_A + 2 * CH_B;

    auto load_stage = [&](int t) {
        unsigned sb = smemBase + (unsigned)((t % STAGES) * STAGE_BYTES);
        int k0 = t * BK;
        #pragma unroll
        for (int c = tid; c < TOT; c += NT) {
            int cc = c; const bf16* gp; unsigned soff;
            if (cc < CH_A) {
                int r = cc >> 2, o = cc & 3;
                gp = Ah + (size_t)r * lda + k0 + o * 8;
                soff = (unsigned)(r * RB + o * 16);
            } else if (cc < 2 * CH_A) {
                cc -= CH_A; int r = cc >> 2, o = cc & 3;
                gp = Al + (size_t)r * lda + k0 + o * 8;
                soff = OFF_AL + (unsigned)(r * RB + o * 16);
            } else if (cc < 2 * CH_A + CH_B) {
                cc -= 2 * CH_A; int r = cc >> 2, o = cc & 3;
                gp = Bh + (size_t)r * ldb + k0 + o * 8;
                soff = OFF_BH + (unsigned)(r * RB + o * 16);
            } else {
                cc -= 2 * CH_A + CH_B; int r = cc >> 2, o = cc & 3;
                gp = Bl + (size_t)r * ldb + k0 + o * 8;
                soff = OFF_BL + (unsigned)(r * RB + o * 16);
            }
            cp16(sb + soff, gp);
        }
    };

    float acc[MF][NF][4] = {};

    // prologue
    #pragma unroll
    for (int s = 0; s < STAGES - 1; s++) {
        if (s < KT) { load_stage(s); cp_commit(); }
    }

    int arow = lane & 15;
    int acol = (lane >> 4) << 4;
    int nrow = (lane & 7) | ((lane & 16) >> 1);
    int ncol = (lane & 8) ? 16 : 0;

    for (int t = 0; t < KT; t++) {
        if (t + STAGES - 1 < KT) cp_wait<STAGES - 2>(); else cp_wait<0>();
        __syncthreads();
        if (t + STAGES - 1 < KT) { load_stage(t + STAGES - 1); cp_commit(); }

        unsigned sb = smemBase + (unsigned)((t % STAGES) * STAGE_BYTES);
        #pragma unroll
        for (int kk = 0; kk < 2; kk++) {
            unsigned ah[MF][4], al[MF][4], bh[NF2][4], bl[NF2][4];
            #pragma unroll
            for (int mi = 0; mi < MF; mi++) {
                unsigned base = sb + (unsigned)((wm * WM + mi * 16 + arow) * RB + kk * 32 + acol);
                ldsm4(ah[mi][0], ah[mi][1], ah[mi][2], ah[mi][3], base);
                ldsm4(al[mi][0], al[mi][1], al[mi][2], al[mi][3], base + OFF_AL);
            }
            #pragma unroll
            for (int j = 0; j < NF2; j++) {
                unsigned base = sb + OFF_BH + (unsigned)((wn * WN + j * 16 + nrow) * RB + kk * 32 + ncol);
                ldsm4(bh[j][0], bh[j][1], bh[j][2], bh[j][3], base);
                ldsm4(bl[j][0], bl[j][1], bl[j][2], bl[j][3], base + (OFF_BL - OFF_BH));
            }
            #pragma unroll
            for (int mi = 0; mi < MF; mi++)
                #pragma unroll
                for (int ni = 0; ni < NF; ni++) {
                    int j = ni >> 1, o = (ni & 1) * 2;
                    MMA16(acc[mi][ni], ah[mi], bh[j][o], bh[j][o + 1]);
                    MMA16(acc[mi][ni], ah[mi], bl[j][o], bl[j][o + 1]);
                    MMA16(acc[mi][ni], al[mi], bh[j][o], bh[j][o + 1]);
                }
        }
    }

    // ---- epilogue ----
    float* Cfb = Cf ? Cf + (size_t)bz * sCb + (size_t)hz * sCh : nullptr;
    bf16* Chb = Chi ? Chi + (size_t)bz * sCb + (size_t)hz * sCh : nullptr;
    bf16* Clb = Clo ? Clo + (size_t)bz * sCb + (size_t)hz * sCh : nullptr;

    #pragma unroll
    for (int mi = 0; mi < MF; mi++) {
        #pragma unroll
        for (int ni = 0; ni < NF; ni++) {
            int r0 = row0 + wm * WM + mi * 16 + (lane >> 2);
            int cn = n0 + wn * WN + ni * 8 + 2 * (lane & 3);
            #pragma unroll
            for (int half = 0; half < 2; half++) {
                int r = r0 + half * 8;
                float v0 = acc[mi][ni][half * 2 + 0] * alpha;
                float v1 = acc[mi][ni][half * 2 + 1] * alpha;
                if (epi == 0) {
                    *(float2*)(Cfb + (size_t)r * ldc + cn) = make_float2(v0, v1);
                } else if (epi == 1) {
                    size_t off = (size_t)r * ldc + cn;
                    bf16 h0, l0, h1, l1; split2(v0, h0, l0); split2(v1, h1, l1);
                    __nv_bfloat162 ph; ph.x = h0; ph.y = h1;
                    __nv_bfloat162 pl; pl.x = l0; pl.y = l1;
                    *(__nv_bfloat162*)(Chb + off) = ph;
                    *(__nv_bfloat162*)(Clb + off) = pl;
                } else if (epi == 2) {
                    size_t off = (size_t)r * ldc + cn;
                    float2 old = *(float2*)(Cfb + off);
                    old.x += (v0 + bias[cn]) * LSCALE;
                    old.y += (v1 + bias[cn + 1]) * LSCALE;
                    *(float2*)(Cfb + off) = old;
                } else if (epi == 3) {
                    // v proj: row = b*512+i, col cn = h*64+d -> vT[(b*768+cn)*512 + i]
                    int bb = r >> 9, ii = r & 511;
                    size_t idx = ((size_t)bb * 768 + cn) * 512 + ii;
                    bf16 h0, l0, h1, l1; split2(v0, h0, l0); split2(v1, h1, l1);
                    Chb[idx] = h0; Clb[idx] = l0;
                    Chb[idx + 512] = h1; Clb[idx + 512] = l1;
                } else {
                    size_t off = (size_t)r * ldc + cn;
                    float t0 = gelu_tanh(v0 + bias[cn]);
                    float t1 = gelu_tanh(v1 + bias[cn + 1]);
                    bf16 h0, l0, h1, l1; split2(t0, h0, l0); split2(t1, h1, l1);
                    __nv_bfloat162 ph; ph.x = h0; ph.y = h1;
                    __nv_bfloat162 pl; pl.x = l0; pl.y = l1;
                    *(__nv_bfloat162*)(Chb + off) = ph;
                    *(__nv_bfloat162*)(Clb + off) = pl;
                }
            }
        }
    }
}

// ---------------- launch ----------------
extern "C" void kernel_launch(void* const* d_in, const int* in_sizes, int n_in,
                              void* d_out, int out_size) {
    const float* x_in     = (const float*)d_in[0];
    const float* ln1      = (const float*)d_in[1];
    const float* Wq       = (const float*)d_in[2];
    const float* Wkv      = (const float*)d_in[3];
    const float* mix_pre  = (const float*)d_in[4];
    const float* mix_post = (const float*)d_in[5];
    const float* Wo       = (const float*)d_in[6];
    const float* bo       = (const float*)d_in[7];
    const float* ln2      = (const float*)d_in[8];
    const float* W1       = (const float*)d_in[9];
    const float* b1       = (const float*)d_in[10];
    const float* W2       = (const float*)d_in[11];
    const float* b2       = (const float*)d_in[12];

    float* X = (float*)d_out;

    bf16 *h_hi, *h_lo, *q_hi, *q_lo, *k_hi, *k_lo, *vT_hi, *vT_lo;
    bf16 *at_hi, *at_lo, *o_hi, *o_lo, *m_hi, *m_lo;
    bf16 *wqT_hi, *wqT_lo, *wkT_hi, *wkT_lo, *wvT_hi, *wvT_lo;
    bf16 *woT_hi, *woT_lo, *w1T_hi, *w1T_lo, *w2T_hi, *w2T_lo;
    float* dots;
    cudaGetSymbolAddress((void**)&h_hi, g_h_hi);   cudaGetSymbolAddress((void**)&h_lo, g_h_lo);
    cudaGetSymbolAddress((void**)&q_hi, g_q_hi);   cudaGetSymbolAddress((void**)&q_lo, g_q_lo);
    cudaGetSymbolAddress((void**)&k_hi, g_k_hi);   cudaGetSymbolAddress((void**)&k_lo, g_k_lo);
    cudaGetSymbolAddress((void**)&vT_hi, g_vT_hi); cudaGetSymbolAddress((void**)&vT_lo, g_vT_lo);
    cudaGetSymbolAddress((void**)&at_hi, g_at_hi); cudaGetSymbolAddress((void**)&at_lo, g_at_lo);
    cudaGetSymbolAddress((void**)&o_hi, g_o_hi);   cudaGetSymbolAddress((void**)&o_lo, g_o_lo);
    cudaGetSymbolAddress((void**)&m_hi, g_m_hi);   cudaGetSymbolAddress((void**)&m_lo, g_m_lo);
    cudaGetSymbolAddress((void**)&wqT_hi, g_wqT_hi); cudaGetSymbolAddress((void**)&wqT_lo, g_wqT_lo);
    cudaGetSymbolAddress((void**)&wkT_hi, g_wkT_hi); cudaGetSymbolAddress((void**)&wkT_lo, g_wkT_lo);
    cudaGetSymbolAddress((void**)&wvT_hi, g_wvT_hi); cudaGetSymbolAddress((void**)&wvT_lo, g_wvT_lo);
    cudaGetSymbolAddress((void**)&woT_hi, g_woT_hi); cudaGetSymbolAddress((void**)&woT_lo, g_woT_lo);
    cudaGetSymbolAddress((void**)&w1T_hi, g_w1T_hi); cudaGetSymbolAddress((void**)&w1T_lo, g_w1T_lo);
    cudaGetSymbolAddress((void**)&w2T_hi, g_w2T_hi); cudaGetSymbolAddress((void**)&w2T_lo, g_w2T_lo);
    cudaGetSymbolAddress((void**)&dots, g_dots);

    const int SM128 = (2 * 128 + 2 * 128) * 80 * 3;   // 122880
    const int SM64  = (2 * 128 + 2 * 64) * 80 * 3;    //  92160
    cudaFuncSetAttribute((const void*)tgemm_bf<128, 128, 2, 4>,
                         cudaFuncAttributeMaxDynamicSharedMemorySize, SM128);
    cudaFuncSetAttribute((const void*)tgemm_bf<128, 64, 4, 2>,
                         cudaFuncAttributeMaxDynamicSharedMemorySize, SM64);

    cudaMemcpyAsync(X, x_in, (size_t)ROWS * DIM * sizeof(float),
                    cudaMemcpyDeviceToDevice);

    // ---- weight transpose+split (all layers) ----
    dim3 tb(32, 8);
    for (int d = 0; d < DEPTH; d++) {
        size_t wo768 = (size_t)d * DIM * INNER;
        wsplit_t<<<dim3(DIM / 32, INNER / 32), tb>>>(Wq + wo768, INNER, DIM, INNER,
                                                     wqT_hi + wo768, wqT_lo + wo768);
        wsplit_t<<<dim3(DIM / 32, INNER / 32), tb>>>(Wkv + (size_t)d * DIM * 2 * INNER,
                                                     2 * INNER, DIM, INNER,
                                                     wkT_hi + wo768, wkT_lo + wo768);
        wsplit_t<<<dim3(DIM / 32, INNER / 32), tb>>>(Wkv + (size_t)d * DIM * 2 * INNER + INNER,
                                                     2 * INNER, DIM, INNER,
                                                     wvT_hi + wo768, wvT_lo + wo768);
        wsplit_t<<<dim3(INNER / 32, DIM / 32), tb>>>(Wo + wo768, DIM, INNER, DIM,
                                                     woT_hi + wo768, woT_lo + wo768);
        size_t w1o = (size_t)d * DIM * MLPDIM;
        wsplit_t<<<dim3(DIM / 32, MLPDIM / 32), tb>>>(W1 + w1o, MLPDIM, DIM, MLPDIM,
                                                      w1T_hi + w1o, w1T_lo + w1o);
        wsplit_t<<<dim3(MLPDIM / 32, DIM / 32), tb>>>(W2 + w1o, DIM, MLPDIM, DIM,
                                                      w2T_hi + w1o, w2T_lo + w1o);
    }

    for (int d = 0; d < DEPTH; d++) {
        size_t wo768 = (size_t)d * DIM * INNER;
        size_t w1o = (size_t)d * DIM * MLPDIM;

        // ---- attention half ----
        ln_split<<<ROWS, 256>>>(X, ln1 + d * DIM, h_hi, h_lo);

        tgemm_bf<128, 128, 2, 4><<<dim3(INNER / 128, ROWS / 128, 1), 256, SM128>>>(
            h_hi, h_lo, DIM, 0, 0,
            wqT_hi + wo768, wqT_lo + wo768, DIM, 0, 0,
            nullptr, q_hi, q_lo, INNER, 0, 0, nullptr,
            ROWS, INNER, DIM, 1, 1.f, 1);
        tgemm_bf<128, 128, 2, 4><<<dim3(INNER / 128, ROWS / 128, 1), 256, SM128>>>(
            h_hi, h_lo, DIM, 0, 0,
            wkT_hi + wo768, wkT_lo + wo768, DIM, 0, 0,
            nullptr, k_hi, k_lo, INNER, 0, 0, nullptr,
            ROWS, INNER, DIM, 1, 1.f, 1);
        tgemm_bf<128, 128, 2, 4><<<dim3(INNER / 128, ROWS / 128, 1), 256, SM128>>>(
            h_hi, h_lo, DIM, 0, 0,
            wvT_hi + wo768, wvT_lo + wo768, DIM, 0, 0,
            nullptr, vT_hi, vT_lo, 0, 0, 0, nullptr,
            ROWS, INNER, DIM, 1, 1.f, 3);

        // dots = scale * q @ k^T  per (b,h)
        tgemm_bf<128, 128, 2, 4><<<dim3(SEQ / 128, SEQ / 128, BATCH * NHEAD), 256, SM128>>>(
            q_hi, q_lo, INNER, (long)SEQ * INNER, DH,
            k_hi, k_lo, INNER, (long)SEQ * INNER, DH,
            dots, nullptr, nullptr, SEQ, (long)NHEAD * SSQ, (long)SSQ, nullptr,
            SEQ, SEQ, DH, NHEAD, ATT_SCALE, 0);

        attn_mix_softmax<<<BATCH * SEQ, 384>>>(dots, mix_pre + d * NHEAD * NHEAD,
                                               mix_post + d * NHEAD * NHEAD, at_hi, at_lo);

        // o = attn @ v   (v pre-transposed)
        tgemm_bf<128, 64, 4, 2><<<dim3(1, SEQ / 128, BATCH * NHEAD), 256, SM64>>>(
            at_hi, at_lo, SEQ, (long)NHEAD * SSQ, (long)SSQ,
            vT_hi, vT_lo, SEQ, (long)NHEAD * DH * SEQ, (long)DH * SEQ,
            nullptr, o_hi, o_lo, INNER, (long)SEQ * INNER, DH, nullptr,
            SEQ, DH, SEQ, NHEAD, 1.f, 1);

        // X += (o @ Wo + bo) * LS
        tgemm_bf<128, 128, 2, 4><<<dim3(DIM / 128, ROWS / 128, 1), 256, SM128>>>(
            o_hi, o_lo, INNER, 0, 0,
            woT_hi + wo768, woT_lo + wo768, INNER, 0, 0,
            X, nullptr, nullptr, DIM, 0, 0, bo + d * DIM,
            ROWS, DIM, INNER, 1, 1.f, 2);

        // ---- MLP half ----
        ln_split<<<ROWS, 256>>>(X, ln2 + d * DIM, h_hi, h_lo);

        tgemm_bf<128, 128, 2, 4><<<dim3(MLPDIM / 128, ROWS / 128, 1), 256, SM128>>>(
            h_hi, h_lo, DIM, 0, 0,
            w1T_hi + w1o, w1T_lo + w1o, DIM, 0, 0,
            nullptr, m_hi, m_lo, MLPDIM, 0, 0, b1 + d * MLPDIM,
            ROWS, MLPDIM, DIM, 1, 1.f, 4);

        tgemm_bf<128, 128, 2, 4><<<dim3(DIM / 128, ROWS / 128, 1), 256, SM128>>>(
            m_hi, m_lo, MLPDIM, 0, 0,
            w2T_hi + w1o, w2T_lo + w1o, MLPDIM, 0, 0,
            X, nullptr, nullptr, DIM, 0, 0, b2 + d * DIM,
            ROWS, DIM, MLPDIM, 1, 1.f, 2);
    }
}

// round 6
// speedup vs baseline: 3.7101x; 1.4391x over previous
#include <cuda_runtime.h>
#include <cuda_bf16.h>
#include <math.h>
#include <stdint.h>

#define BATCH 8
#define SEQ 512
#define DIM 768
#define NHEAD 12
#define DH 64
#define INNER 768
#define MLPDIM 3072
#define DEPTH 4
#define ROWS (BATCH * SEQ)
#define LSCALE 0.1f
#define EPS 1e-5f
#define ATT_SCALE 0.125f
#define SSQ (SEQ * SEQ)

typedef __nv_bfloat16 bf16;

// ---------------- scratch (device globals) ----------------
__device__ bf16 g_h_hi [ROWS * DIM],    g_h_lo [ROWS * DIM];
__device__ bf16 g_q_hi [ROWS * INNER],  g_q_lo [ROWS * INNER];
__device__ bf16 g_k_hi [ROWS * INNER];
__device__ bf16 g_vT_hi[ROWS * INNER];
__device__ float g_dots[BATCH * NHEAD * SSQ];
__device__ bf16 g_at_hi[BATCH * NHEAD * SSQ], g_at_lo[BATCH * NHEAD * SSQ];
__device__ bf16 g_o_hi [ROWS * INNER],  g_o_lo [ROWS * INNER];
__device__ bf16 g_m_hi [ROWS * MLPDIM], g_m_lo [ROWS * MLPDIM];
// transposed weights (hi only — B operand is single bf16 now)
__device__ bf16 g_wqT_hi[DEPTH * DIM * INNER];
__device__ bf16 g_wkT_hi[DEPTH * DIM * INNER];
__device__ bf16 g_wvT_hi[DEPTH * DIM * INNER];
__device__ bf16 g_woT_hi[DEPTH * INNER * DIM];
__device__ bf16 g_w1T_hi[DEPTH * DIM * MLPDIM];
__device__ bf16 g_w2T_hi[DEPTH * MLPDIM * DIM];

__device__ __forceinline__ float gelu_tanh(float x) {
    float x3 = x * x * x;
    return 0.5f * x * (1.0f + tanhf(0.7978845608028654f * (x + 0.044715f * x3)));
}
__device__ __forceinline__ void split2(float v, bf16& h, bf16& l) {
    h = __float2bfloat16(v);
    l = __float2bfloat16(v - __bfloat162float(h));
}

__device__ __forceinline__ void cp16(unsigned s, const void* g) {
    asm volatile("cp.async.cg.shared.global [%0], [%1], 16;\n" :: "r"(s), "l"(g));
}
__device__ __forceinline__ void cp_commit() {
    asm volatile("cp.async.commit_group;\n");
}
template<int N> __device__ __forceinline__ void cp_wait() {
    asm volatile("cp.async.wait_group %0;\n" :: "n"(N));
}
__device__ __forceinline__ void ldsm4(unsigned& r0, unsigned& r1, unsigned& r2,
                                      unsigned& r3, unsigned addr) {
    asm volatile("ldmatrix.sync.aligned.m8n8.x4.shared.b16 {%0,%1,%2,%3}, [%4];\n"
                 : "=r"(r0), "=r"(r1), "=r"(r2), "=r"(r3) : "r"(addr));
}
#define MMA16(d, a, b0, b1) \
    asm volatile("mma.sync.aligned.m16n8k16.row.col.f32.bf16.bf16.f32 " \
                 "{%0,%1,%2,%3},{%4,%5,%6,%7},{%8,%9},{%0,%1,%2,%3};\n" \
                 : "+f"(d[0]), "+f"(d[1]), "+f"(d[2]), "+f"(d[3])       \
                 : "r"(a[0]), "r"(a[1]), "r"(a[2]), "r"(a[3]), "r"(b0), "r"(b1))

// ---------------- transpose weights -> bf16 hi only ----------------
__global__ __launch_bounds__(256) void wsplit_t(const float* __restrict__ in, int ldin,
                                                int K, int N, bf16* __restrict__ oh) {
    __shared__ float t[32][33];
    int tx = threadIdx.x, ty = threadIdx.y;
    int k0 = blockIdx.x * 32, n0 = blockIdx.y * 32;
    #pragma unroll
    for (int r = ty; r < 32; r += 8)
        t[r][tx] = in[(size_t)(k0 + r) * ldin + n0 + tx];
    __syncthreads();
    #pragma unroll
    for (int r = ty; r < 32; r += 8) {
        int n = n0 + r, k = k0 + tx;
        oh[(size_t)n * K + k] = __float2bfloat16(t[tx][r]);
    }
}

// ---------------- LayerNorm -> split ----------------
__global__ __launch_bounds__(256) void ln_split(const float* __restrict__ x,
                                                const float* __restrict__ scale,
                                                bf16* __restrict__ oh, bf16* __restrict__ ol) {
    int row = blockIdx.x;
    const float* xr = x + (size_t)row * DIM;
    int tid = threadIdx.x;
    float s = 0.f, s2 = 0.f;
    for (int c = tid; c < DIM; c += 256) { float v = xr[c]; s += v; s2 += v * v; }
    __shared__ float rs[256], rs2[256];
    rs[tid] = s; rs2[tid] = s2;
    __syncthreads();
    for (int off = 128; off > 0; off >>= 1) {
        if (tid < off) { rs[tid] += rs[tid + off]; rs2[tid] += rs2[tid + off]; }
        __syncthreads();
    }
    float mu = rs[0] * (1.0f / DIM);
    float var = rs2[0] * (1.0f / DIM) - mu * mu;
    float rstd = rsqrtf(var + EPS);
    for (int c = tid; c < DIM; c += 256) {
        float v = (xr[c] - mu) * rstd * scale[c];
        bf16 h, l; split2(v, h, l);
        size_t idx = (size_t)row * DIM + c;
        oh[idx] = h; ol[idx] = l;
    }
}

// ---------------- fused mix_pre -> softmax -> mix_post -> split ----------------
__global__ __launch_bounds__(384) void attn_mix_softmax(
    const float* __restrict__ dots, const float* __restrict__ mp,
    const float* __restrict__ mq, bf16* __restrict__ ah, bf16* __restrict__ al)
{
    __shared__ float S[NHEAD][SEQ];
    __shared__ float T[NHEAD][SEQ];
    int tid = threadIdx.x, lane = tid & 31, g = tid >> 5;
    int b = blockIdx.x >> 9, i = blockIdx.x & 511;
    const float* base = dots + ((size_t)(b * NHEAD) * SEQ + i) * SEQ;

    #pragma unroll
    for (int it = 0; it < 4; it++) {
        int idx = tid + it * 384;
        int h = idx >> 7, jq = (idx & 127) << 2;
        *(float4*)&S[h][jq] = *(const float4*)(base + (size_t)h * SSQ + jq);
    }
    __syncthreads();

    float mcol[NHEAD];
    #pragma unroll
    for (int h = 0; h < NHEAD; h++) mcol[h] = __ldg(&mp[h * NHEAD + g]);
    float v[16];
    float mx = -1e30f;
    #pragma unroll
    for (int k = 0; k < 16; k++) {
        int j = lane + k * 32;
        float a = 0.f;
        #pragma unroll
        for (int h = 0; h < NHEAD; h++) a += S[h][j] * mcol[h];
        v[k] = a; mx = fmaxf(mx, a);
    }
    #pragma unroll
    for (int off = 16; off > 0; off >>= 1)
        mx = fmaxf(mx, __shfl_xor_sync(0xffffffffu, mx, off));
    float s = 0.f;
    #pragma unroll
    for (int k = 0; k < 16; k++) { v[k] = __expf(v[k] - mx); s += v[k]; }
    #pragma unroll
    for (int off = 16; off > 0; off >>= 1)
        s += __shfl_xor_sync(0xffffffffu, s, off);
    float inv = 1.0f / s;
    #pragma unroll
    for (int k = 0; k < 16; k++) T[g][lane + k * 32] = v[k] * inv;
    __syncthreads();

    float qcol[NHEAD];
    #pragma unroll
    for (int h = 0; h < NHEAD; h++) qcol[h] = __ldg(&mq[h * NHEAD + g]);
    size_t ob = ((size_t)((b * NHEAD + g) * SEQ) + i) * SEQ;
    #pragma unroll
    for (int k = 0; k < 16; k++) {
        int j = lane + k * 32;
        float a = 0.f;
        #pragma unroll
        for (int h = 0; h < NHEAD; h++) a += T[h][j] * qcol[h];
        bf16 hh, ll; split2(a, hh, ll);
        ah[ob + j] = hh; al[ob + j] = ll;
    }
}

// ---------------- bf16 2-term split GEMM, BK=64, 3-stage cp.async ----------
// A[m][k] split hi/lo (exact), B[n][k] single bf16 (rounded). acc f32.
// epi: 0 f32 store*alpha   1 split-store    2 X += (v+bias)*LS
//      3 vT scatter (hi)   4 gelu split     5 hi-only store
template<int BN, int WARPS_M, int WARPS_N>
__global__ __launch_bounds__(256) void tgemm2(
    const bf16* __restrict__ Ahp, const bf16* __restrict__ Alp, int lda, long sAb, long sAh,
    const bf16* __restrict__ Bhp, int ldb, long sBb, long sBh,
    float* __restrict__ Cf, bf16* __restrict__ Chi, bf16* __restrict__ Clo,
    int ldc, long sCb, long sCh, const float* __restrict__ bias,
    int K, int nH, float alpha, int epi)
{
    constexpr int BM = 128, BK = 64, STAGES = 3;
    constexpr int RB = 144;                       // 128B data + 16B pad per row
    constexpr unsigned OFF_AL = BM * RB;
    constexpr unsigned OFF_B  = 2u * BM * RB;
    constexpr unsigned STAGE  = (2 * BM + BN) * RB;
    constexpr int WM = BM / WARPS_M, WN = BN / WARPS_N;
    constexpr int MF = WM / 16, NF = WN / 8, NF2 = NF / 2;

    extern __shared__ __align__(16) char ds[];
    unsigned sb0 = (unsigned)__cvta_generic_to_shared(ds);

    int tid = threadIdx.x, lane = tid & 31, warp = tid >> 5;
    int wm = warp / WARPS_N, wn = warp % WARPS_N;
    int bz = blockIdx.z / nH, hz = blockIdx.z % nH;
    int row0 = blockIdx.y * BM, n0 = blockIdx.x * BN;

    const bf16* Ah = Ahp + (size_t)bz * sAb + (size_t)hz * sAh + (size_t)row0 * lda;
    const bf16* Al = Alp + (size_t)bz * sAb + (size_t)hz * sAh + (size_t)row0 * lda;
    const bf16* Bh = Bhp + (size_t)bz * sBb + (size_t)hz * sBh + (size_t)n0 * ldb;

    const int KT = K / BK;
    constexpr int TOT = (2 * BM + BN) * 8;        // 16B chunks per stage

    auto load_stage = [&](int t) {
        unsigned sbm = sb0 + (unsigned)(t % STAGES) * STAGE;
        int k0 = t * BK;
        #pragma unroll
        for (int c = tid; c < TOT; c += 256) {
            int cc = c; const bf16* g; unsigned reg; int ld;
            if (cc < BM * 8)          { g = Ah; reg = 0;      ld = lda; }
            else if (cc < 2 * BM * 8) { cc -= BM * 8; g = Al; reg = OFF_AL; ld = lda; }
            else                      { cc -= 2 * BM * 8; g = Bh; reg = OFF_B; ld = ldb; }
            int r = cc >> 3, q = cc & 7;
            cp16(sbm + reg + (unsigned)(r * RB + q * 16),
                 g + (size_t)r * ld + k0 + q * 8);
        }
    };

    float acc[MF][NF][4] = {};

    #pragma unroll
    for (int s = 0; s < STAGES - 1; s++)
        if (s < KT) { load_stage(s); cp_commit(); }

    int arow = lane & 15;
    int acol = (lane >> 4) << 4;
    int nrow = (lane & 7) | ((lane & 16) >> 1);
    int ncol = (lane & 8) ? 16 : 0;

    for (int t = 0; t < KT; t++) {
        if (t + 1 < KT) cp_wait<1>(); else cp_wait<0>();
        __syncthreads();
        if (t + STAGES - 1 < KT) { load_stage(t + STAGES - 1); cp_commit(); }

        unsigned sbm = sb0 + (unsigned)(t % STAGES) * STAGE;
        #pragma unroll
        for (int kk = 0; kk < BK / 16; kk++) {
            unsigned ah[MF][4], al[MF][4], bh[NF2][4];
            #pragma unroll
            for (int mi = 0; mi < MF; mi++) {
                unsigned base = sbm + (unsigned)((wm * WM + mi * 16 + arow) * RB + kk * 32 + acol);
                ldsm4(ah[mi][0], ah[mi][1], ah[mi][2], ah[mi][3], base);
                ldsm4(al[mi][0], al[mi][1], al[mi][2], al[mi][3], base + OFF_AL);
            }
            #pragma unroll
            for (int j = 0; j < NF2; j++) {
                unsigned base = sbm + OFF_B + (unsigned)((wn * WN + j * 16 + nrow) * RB + kk * 32 + ncol);
                ldsm4(bh[j][0], bh[j][1], bh[j][2], bh[j][3], base);
            }
            #pragma unroll
            for (int mi = 0; mi < MF; mi++)
                #pragma unroll
                for (int ni = 0; ni < NF; ni++) {
                    int j = ni >> 1, o = (ni & 1) * 2;
                    MMA16(acc[mi][ni], ah[mi], bh[j][o], bh[j][o + 1]);
                    MMA16(acc[mi][ni], al[mi], bh[j][o], bh[j][o + 1]);
                }
        }
    }

    // ---- epilogue ----
    float* Cfb = Cf ? Cf + (size_t)bz * sCb + (size_t)hz * sCh : nullptr;
    bf16* Chb = Chi ? Chi + (size_t)bz * sCb + (size_t)hz * sCh : nullptr;
    bf16* Clb = Clo ? Clo + (size_t)bz * sCb + (size_t)hz * sCh : nullptr;

    #pragma unroll
    for (int mi = 0; mi < MF; mi++) {
        #pragma unroll
        for (int ni = 0; ni < NF; ni++) {
            int r0 = row0 + wm * WM + mi * 16 + (lane >> 2);
            int cn = n0 + wn * WN + ni * 8 + 2 * (lane & 3);
            #pragma unroll
            for (int half = 0; half < 2; half++) {
                int r = r0 + half * 8;
                float v0 = acc[mi][ni][half * 2 + 0] * alpha;
                float v1 = acc[mi][ni][half * 2 + 1] * alpha;
                if (epi == 0) {
                    *(float2*)(Cfb + (size_t)r * ldc + cn) = make_float2(v0, v1);
                } else if (epi == 1) {
                    size_t off = (size_t)r * ldc + cn;
                    bf16 h0, l0, h1, l1; split2(v0, h0, l0); split2(v1, h1, l1);
                    __nv_bfloat162 ph; ph.x = h0; ph.y = h1;
                    __nv_bfloat162 pl; pl.x = l0; pl.y = l1;
                    *(__nv_bfloat162*)(Chb + off) = ph;
                    *(__nv_bfloat162*)(Clb + off) = pl;
                } else if (epi == 2) {
                    size_t off = (size_t)r * ldc + cn;
                    float2 old = *(float2*)(Cfb + off);
                    old.x += (v0 + bias[cn]) * LSCALE;
                    old.y += (v1 + bias[cn + 1]) * LSCALE;
                    *(float2*)(Cfb + off) = old;
                } else if (epi == 3) {
                    int bb = r >> 9, ii = r & 511;
                    size_t idx = ((size_t)bb * INNER + cn) * SEQ + ii;
                    Chb[idx] = __float2bfloat16(v0);
                    Chb[idx + SEQ] = __float2bfloat16(v1);
                } else if (epi == 4) {
                    size_t off = (size_t)r * ldc + cn;
                    float t0 = gelu_tanh(v0 + bias[cn]);
                    float t1 = gelu_tanh(v1 + bias[cn + 1]);
                    bf16 h0, l0, h1, l1; split2(t0, h0, l0); split2(t1, h1, l1);
                    __nv_bfloat162 ph; ph.x = h0; ph.y = h1;
                    __nv_bfloat162 pl; pl.x = l0; pl.y = l1;
                    *(__nv_bfloat162*)(Chb + off) = ph;
                    *(__nv_bfloat162*)(Clb + off) = pl;
                } else {   // 5: hi-only store
                    size_t off = (size_t)r * ldc + cn;
                    __nv_bfloat162 ph;
                    ph.x = __float2bfloat16(v0); ph.y = __float2bfloat16(v1);
                    *(__nv_bfloat162*)(Chb + off) = ph;
                }
            }
        }
    }
}

// ---------------- launch ----------------
extern "C" void kernel_launch(void* const* d_in, const int* in_sizes, int n_in,
                              void* d_out, int out_size) {
    const float* x_in     = (const float*)d_in[0];
    const float* ln1      = (const float*)d_in[1];
    const float* Wq       = (const float*)d_in[2];
    const float* Wkv      = (const float*)d_in[3];
    const float* mix_pre  = (const float*)d_in[4];
    const float* mix_post = (const float*)d_in[5];
    const float* Wo       = (const float*)d_in[6];
    const float* bo       = (const float*)d_in[7];
    const float* ln2      = (const float*)d_in[8];
    const float* W1       = (const float*)d_in[9];
    const float* b1       = (const float*)d_in[10];
    const float* W2       = (const float*)d_in[11];
    const float* b2       = (const float*)d_in[12];

    float* X = (float*)d_out;

    bf16 *h_hi, *h_lo, *q_hi, *q_lo, *k_hi, *vT_hi;
    bf16 *at_hi, *at_lo, *o_hi, *o_lo, *m_hi, *m_lo;
    bf16 *wqT, *wkT, *wvT, *woT, *w1T, *w2T;
    float* dots;
    cudaGetSymbolAddress((void**)&h_hi, g_h_hi);   cudaGetSymbolAddress((void**)&h_lo, g_h_lo);
    cudaGetSymbolAddress((void**)&q_hi, g_q_hi);   cudaGetSymbolAddress((void**)&q_lo, g_q_lo);
    cudaGetSymbolAddress((void**)&k_hi, g_k_hi);
    cudaGetSymbolAddress((void**)&vT_hi, g_vT_hi);
    cudaGetSymbolAddress((void**)&at_hi, g_at_hi); cudaGetSymbolAddress((void**)&at_lo, g_at_lo);
    cudaGetSymbolAddress((void**)&o_hi, g_o_hi);   cudaGetSymbolAddress((void**)&o_lo, g_o_lo);
    cudaGetSymbolAddress((void**)&m_hi, g_m_hi);   cudaGetSymbolAddress((void**)&m_lo, g_m_lo);
    cudaGetSymbolAddress((void**)&wqT, g_wqT_hi);
    cudaGetSymbolAddress((void**)&wkT, g_wkT_hi);
    cudaGetSymbolAddress((void**)&wvT, g_wvT_hi);
    cudaGetSymbolAddress((void**)&woT, g_woT_hi);
    cudaGetSymbolAddress((void**)&w1T, g_w1T_hi);
    cudaGetSymbolAddress((void**)&w2T, g_w2T_hi);
    cudaGetSymbolAddress((void**)&dots, g_dots);

    const int SM128 = 3 * (2 * 128 + 128) * 144;   // 165888
    const int SM64  = 3 * (2 * 128 + 64) * 144;    // 138240
    cudaFuncSetAttribute((const void*)tgemm2<128, 2, 4>,
                         cudaFuncAttributeMaxDynamicSharedMemorySize, SM128);
    cudaFuncSetAttribute((const void*)tgemm2<64, 4, 2>,
                         cudaFuncAttributeMaxDynamicSharedMemorySize, SM64);

    cudaMemcpyAsync(X, x_in, (size_t)ROWS * DIM * sizeof(float),
                    cudaMemcpyDeviceToDevice);

    // ---- weight transpose (hi only) ----
    dim3 tb(32, 8);
    for (int d = 0; d < DEPTH; d++) {
        size_t wo768 = (size_t)d * DIM * INNER;
        size_t w1o = (size_t)d * DIM * MLPDIM;
        wsplit_t<<<dim3(DIM / 32, INNER / 32), tb>>>(Wq + wo768, INNER, DIM, INNER, wqT + wo768);
        wsplit_t<<<dim3(DIM / 32, INNER / 32), tb>>>(Wkv + (size_t)d * DIM * 2 * INNER,
                                                     2 * INNER, DIM, INNER, wkT + wo768);
        wsplit_t<<<dim3(DIM / 32, INNER / 32), tb>>>(Wkv + (size_t)d * DIM * 2 * INNER + INNER,
                                                     2 * INNER, DIM, INNER, wvT + wo768);
        wsplit_t<<<dim3(INNER / 32, DIM / 32), tb>>>(Wo + wo768, DIM, INNER, DIM, woT + wo768);
        wsplit_t<<<dim3(DIM / 32, MLPDIM / 32), tb>>>(W1 + w1o, MLPDIM, DIM, MLPDIM, w1T + w1o);
        wsplit_t<<<dim3(MLPDIM / 32, DIM / 32), tb>>>(W2 + w1o, DIM, MLPDIM, DIM, w2T + w1o);
    }

    for (int d = 0; d < DEPTH; d++) {
        size_t wo768 = (size_t)d * DIM * INNER;
        size_t w1o = (size_t)d * DIM * MLPDIM;

        // ---- attention half ----
        ln_split<<<ROWS, 256>>>(X, ln1 + d * DIM, h_hi, h_lo);

        // q = h @ Wq (split out)
        tgemm2<128, 2, 4><<<dim3(INNER / 128, ROWS / 128, 1), 256, SM128>>>(
            h_hi, h_lo, DIM, 0, 0,
            wqT + wo768, DIM, 0, 0,
            nullptr, q_hi, q_lo, INNER, 0, 0, nullptr,
            DIM, 1, 1.f, 1);
        // k = h @ Wk (hi only)
        tgemm2<128, 2, 4><<<dim3(INNER / 128, ROWS / 128, 1), 256, SM128>>>(
            h_hi, h_lo, DIM, 0, 0,
            wkT + wo768, DIM, 0, 0,
            nullptr, k_hi, nullptr, INNER, 0, 0, nullptr,
            DIM, 1, 1.f, 5);
        // vT = (h @ Wv)^T per head (hi only)
        tgemm2<128, 2, 4><<<dim3(INNER / 128, ROWS / 128, 1), 256, SM128>>>(
            h_hi, h_lo, DIM, 0, 0,
            wvT + wo768, DIM, 0, 0,
            nullptr, vT_hi, nullptr, 0, 0, 0, nullptr,
            DIM, 1, 1.f, 3);

        // dots = scale * q @ k^T per (b,h)
        tgemm2<128, 2, 4><<<dim3(SEQ / 128, SEQ / 128, BATCH * NHEAD), 256, SM128>>>(
            q_hi, q_lo, INNER, (long)SEQ * INNER, DH,
            k_hi, INNER, (long)SEQ * INNER, DH,
            dots, nullptr, nullptr, SEQ, (long)NHEAD * SSQ, (long)SSQ, nullptr,
            DH, NHEAD, ATT_SCALE, 0);

        attn_mix_softmax<<<BATCH * SEQ, 384>>>(dots, mix_pre + d * NHEAD * NHEAD,
                                               mix_post + d * NHEAD * NHEAD, at_hi, at_lo);

        // o = attn @ v (split out)
        tgemm2<64, 4, 2><<<dim3(1, SEQ / 128, BATCH * NHEAD), 256, SM64>>>(
            at_hi, at_lo, SEQ, (long)NHEAD * SSQ, (long)SSQ,
            vT_hi, SEQ, (long)INNER * SEQ, (long)DH * SEQ,
            nullptr, o_hi, o_lo, INNER, (long)SEQ * INNER, DH, nullptr,
            SEQ, NHEAD, 1.f, 1);

        // X += (o @ Wo + bo) * LS
        tgemm2<128, 2, 4><<<dim3(DIM / 128, ROWS / 128, 1), 256, SM128>>>(
            o_hi, o_lo, INNER, 0, 0,
            woT + wo768, INNER, 0, 0,
            X, nullptr, nullptr, DIM, 0, 0, bo + d * DIM,
            INNER, 1, 1.f, 2);

        // ---- MLP half ----
        ln_split<<<ROWS, 256>>>(X, ln2 + d * DIM, h_hi, h_lo);

        tgemm2<128, 2, 4><<<dim3(MLPDIM / 128, ROWS / 128, 1), 256, SM128>>>(
            h_hi, h_lo, DIM, 0, 0,
            w1T + w1o, DIM, 0, 0,
            nullptr, m_hi, m_lo, MLPDIM, 0, 0, b1 + d * MLPDIM,
            DIM, 1, 1.f, 4);

        tgemm2<128, 2, 4><<<dim3(DIM / 128, ROWS / 128, 1), 256, SM128>>>(
            m_hi, m_lo, MLPDIM, 0, 0,
            w2T + w1o, MLPDIM, 0, 0,
            X, nullptr, nullptr, DIM, 0, 0, b2 + d * DIM,
            MLPDIM, 1, 1.f, 2);
    }
}